// round 14
// baseline (speedup 1.0000x reference)
#include <cuda_runtime.h>
#include <cuda_bf16.h>
#include <cstdint>

#define NN 100000
#define NE 400000
#define NG 4096
#define BN_EPS 1e-5f

// ---------------- scratch (device globals; no allocations allowed) ----------------
__device__ float g_Y[NN * 256];        // projection output
__device__ float g_A[NN * 256];        // self + bias + aggregated neighbors
__device__ float g_H1[NN * 256];
__device__ float g_H2[NN * 128];
__device__ float g_H3[NN * 64];
__device__ float g_pool[NG * 64];
__device__ float g_stats[512];         // [0:256) col sums, [256:512) col sumsq (zero at rest)
__device__ float g_coef[512];          // [0:256) scale s, [256:512) shift t
__device__ float g_biasY[256];         // t @ W  (per-N bias for Y output)
__device__ float g_biasA[256];         // t @ W + b (per-N bias for A output)
__device__ uint32_t g_BtHi[373 * 256]; // transposed weight hi tf32 [N,K]
__device__ uint32_t g_BtLo[373 * 256]; // transposed weight lo tf32 [N,K]
__device__ int   g_is64;

// ---------------- dtype detection (int64 vs int32 indices) ----------------
__global__ void detect_dtype(const unsigned int* __restrict__ w, int n) {
    __shared__ int anyNZ;
    if (threadIdx.x == 0) anyNZ = 0;
    __syncthreads();
    for (int i = threadIdx.x; i < n; i += blockDim.x)
        if (w[2 * i + 1] != 0u) anyNZ = 1;
    __syncthreads();
    if (threadIdx.x == 0) g_is64 = (anyNZ == 0) ? 1 : 0;
}

__device__ __forceinline__ int load_idx(const void* p, long long i, int is64) {
    return is64 ? (int)((const long long*)p)[i] : ((const int*)p)[i];
}

__device__ __forceinline__ uint32_t f2tf32(float v) {
    uint32_t u;
    asm("cvt.rna.tf32.f32 %0, %1;" : "=r"(u) : "f"(v));
    return u;
}

__device__ __forceinline__ void split_tf32(float v, uint32_t& hi, uint32_t& lo) {
    hi = f2tf32(v);
    float r = v - __uint_as_float(hi);
    lo = f2tf32(r);
}

__device__ __forceinline__ void cp4(uint32_t dst, const void* src, bool valid) {
    int sz = valid ? 4 : 0;
    asm volatile("cp.async.ca.shared.global [%0], [%1], 4, %2;"
                 :: "r"(dst), "l"(src), "r"(sz) : "memory");
}

__device__ __forceinline__ void cp16(uint32_t dst, const void* src, bool valid) {
    int sz = valid ? 16 : 0;
    asm volatile("cp.async.ca.shared.global [%0], [%1], 16, %2;"
                 :: "r"(dst), "l"(src), "r"(sz) : "memory");
}

// ---------------- weight transpose+split: [K,N] -> hi/lo tf32 [N,K] ----------------
__global__ void transpose_w_split(const float* __restrict__ in,
                                  uint32_t* __restrict__ out_hi,
                                  uint32_t* __restrict__ out_lo,
                                  int K, int N, const float* __restrict__ scale) {
    __shared__ float t[32][33];
    int kx = blockIdx.y * 32, nx = blockIdx.x * 32;
    int x = threadIdx.x, y = threadIdx.y;      // 32 x 8
#pragma unroll
    for (int j = 0; j < 32; j += 8) {
        int k = kx + y + j, n = nx + x;
        float v = 0.f;
        if (k < K && n < N) {
            v = in[(long long)k * N + n];
            if (scale) v *= scale[k];
        }
        t[y + j][x] = v;
    }
    __syncthreads();
#pragma unroll
    for (int j = 0; j < 32; j += 8) {
        int n = nx + y + j, k = kx + x;
        if (n < N && k < K) {
            uint32_t hi, lo;
            split_tf32(t[x][y + j], hi, lo);
            out_hi[(long long)n * K + k] = hi;
            out_lo[(long long)n * K + k] = lo;
        }
    }
}

// ---------------- bias correction: BY[n] = t @ W[:,n]; BA[n] = BY[n] + b[n] ----------------
__global__ void vecmat_bias(const float* __restrict__ W, const float* __restrict__ coef,
                            const float* __restrict__ b,
                            float* __restrict__ BY, float* __restrict__ BA,
                            int K, int N) {
    int n = blockIdx.x * blockDim.x + threadIdx.x;
    if (n >= N) return;
    float s = 0.f;
    for (int k = 0; k < K; k++)
        s = fmaf(coef[256 + k], W[(long long)k * N + n], s);
    BY[n] = s;
    BA[n] = s + b[n];
}

// ---------------- BN coefficients from stats (race-free; re-zero for replay) ----------------
__global__ void bn_coef(int C, const float* __restrict__ g, const float* __restrict__ be,
                        float* __restrict__ stats, float* __restrict__ coef) {
    int c = threadIdx.x;   // 512 threads
    float sum = 0.f, sq = 0.f;
    if (c < C) {
        sum = stats[c];
        sq  = stats[256 + c];           // read BEFORE anyone zeroes
    }
    __syncthreads();                    // all reads complete before zeroing
    stats[c] = 0.f;
    if (c < C) {
        float invN = 1.f / (float)NN;
        float mu = sum * invN;
        float var = fmaf(-mu, mu, sq * invN);
        float s = rsqrtf(var + BN_EPS) * g[c];
        coef[c] = s;
        coef[256 + c] = fmaf(-mu, s, be[c]);
    }
}

// ---------------- 3xTF32 mma.sync GEMM, cp.async double-buffered, 2 CTAs/SM ----------------
// C[M,N] = f(A[M,K]) @ B[N,K]^T with B pre-split into hi/lo tf32 arrays.
// f = relu if RELUIN (at fragment load). epilogue: C = (acc+bias)[relu]; opt C2 = acc+bias2.
// VEC4: 16-byte cp.async staging (requires K % 32 == 0).
// SMEM: As[2][BM*STR] | Bh[2][BN_*STR] | Bl[2][BN_*STR]
template <int BN_, int WM_, int WN_, int RELUIN, int VEC4>
__global__ __launch_bounds__(256, 2)
void mma_gemm(const float* __restrict__ A,
              const uint32_t* __restrict__ BtHi, const uint32_t* __restrict__ BtLo,
              float* __restrict__ C, int M, int N, int K,
              const float* __restrict__ bias, int reluOut,
              float* __restrict__ C2, const float* __restrict__ bias2) {
    constexpr int BM = 128, BK = 32, STR = 36;
    constexpr int MW = BM / WM_;
    constexpr int NW = BN_ / WN_;
    constexpr int MAT = MW / 16;
    constexpr int NAT = NW / 8;
    constexpr int BH_OFF = 2 * BM * STR;
    constexpr int BL_OFF = BH_OFF + 2 * BN_ * STR;
    extern __shared__ float smem[];
    uint32_t smem_u32;
    asm("{ .reg .u64 t; cvta.to.shared.u64 t, %1; cvt.u32.u64 %0, t; }"
        : "=r"(smem_u32) : "l"(smem));

    const int tid = threadIdx.x;
    const int wid = tid >> 5, lane = tid & 31;
    const int gid = lane >> 2, tig = lane & 3;
    const int wm = wid / WN_, wn = wid % WN_;
    const int m0 = blockIdx.y * BM;
    const int n0 = blockIdx.x * BN_;

    float acc[MAT][NAT][4];
#pragma unroll
    for (int i = 0; i < MAT; i++)
#pragma unroll
        for (int j = 0; j < NAT; j++)
#pragma unroll
            for (int q = 0; q < 4; q++) acc[i][j][q] = 0.f;

    const int KT = (K + BK - 1) / BK;

    auto stage = [&](int kt, int b) {
        const int k0 = kt * BK;
        if (VEC4) {
#pragma unroll
            for (int it = 0; it < (BM * 8) / 256; ++it) {
                int i = tid + it * 256;
                int row = i >> 3, c4 = (i & 7) * 4;
                int gm = m0 + row, gk = k0 + c4;
                bool ok = (gm < M);
                long long gi = ok ? ((long long)gm * K + gk) : 0;
                uint32_t d = smem_u32 + (uint32_t)((b * BM * STR + row * STR + c4) * 4);
                cp16(d, A + gi, ok);
            }
#pragma unroll
            for (int it = 0; it < (BN_ * 8) / 256; ++it) {
                int i = tid + it * 256;
                int n = i >> 3, c4 = (i & 7) * 4;
                int gn = n0 + n, gk = k0 + c4;
                bool ok = (gn < N);
                long long gi = ok ? ((long long)gn * K + gk) : 0;
                uint32_t dh = smem_u32 + (uint32_t)((BH_OFF + b * BN_ * STR + n * STR + c4) * 4);
                uint32_t dl = smem_u32 + (uint32_t)((BL_OFF + b * BN_ * STR + n * STR + c4) * 4);
                cp16(dh, BtHi + gi, ok);
                cp16(dl, BtLo + gi, ok);
            }
        } else {
#pragma unroll
            for (int it = 0; it < (BM * BK) / 256; ++it) {
                int i = tid + it * 256;
                int row = i >> 5, col = i & 31;
                int gm = m0 + row, gk = k0 + col;
                bool ok = (gm < M) && (gk < K);
                long long gi = ok ? ((long long)gm * K + gk) : 0;
                uint32_t d = smem_u32 + (uint32_t)((b * BM * STR + row * STR + col) * 4);
                cp4(d, A + gi, ok);
            }
#pragma unroll
            for (int it = 0; it < (BN_ * BK) / 256; ++it) {
                int i = tid + it * 256;
                int n = i >> 5, col = i & 31;
                int gn = n0 + n, gk = k0 + col;
                bool ok = (gn < N) && (gk < K);
                long long gi = ok ? ((long long)gn * K + gk) : 0;
                uint32_t dh = smem_u32 + (uint32_t)((BH_OFF + b * BN_ * STR + n * STR + col) * 4);
                uint32_t dl = smem_u32 + (uint32_t)((BL_OFF + b * BN_ * STR + n * STR + col) * 4);
                cp4(dh, BtHi + gi, ok);
                cp4(dl, BtLo + gi, ok);
            }
        }
        asm volatile("cp.async.commit_group;" ::: "memory");
    };

    stage(0, 0);
    for (int kt = 0; kt < KT; ++kt) {
        if (kt + 1 < KT) {
            stage(kt + 1, (kt + 1) & 1);
            asm volatile("cp.async.wait_group 1;" ::: "memory");
        } else {
            asm volatile("cp.async.wait_group 0;" ::: "memory");
        }
        __syncthreads();

        const float* As = smem + (kt & 1) * BM * STR;
        const uint32_t* Bsh = (const uint32_t*)smem + BH_OFF + (kt & 1) * BN_ * STR;
        const uint32_t* Bsl = (const uint32_t*)smem + BL_OFF + (kt & 1) * BN_ * STR;

#pragma unroll
        for (int ks = 0; ks < 4; ks++) {
            const int ac = ks * 8 + tig;
            uint32_t ah[MAT][4], al[MAT][4];
#pragma unroll
            for (int im = 0; im < MAT; im++) {
                int ar = wm * MW + im * 16 + gid;
                float a0 = As[ar * STR + ac];
                float a1 = As[(ar + 8) * STR + ac];
                float a2 = As[ar * STR + ac + 4];
                float a3 = As[(ar + 8) * STR + ac + 4];
                if (RELUIN) {
                    a0 = fmaxf(a0, 0.f); a1 = fmaxf(a1, 0.f);
                    a2 = fmaxf(a2, 0.f); a3 = fmaxf(a3, 0.f);
                }
                split_tf32(a0, ah[im][0], al[im][0]);
                split_tf32(a1, ah[im][1], al[im][1]);
                split_tf32(a2, ah[im][2], al[im][2]);
                split_tf32(a3, ah[im][3], al[im][3]);
            }
#pragma unroll
            for (int in = 0; in < NAT; in++) {
                // B pre-split: plain LDS, no ALU
                int br = wn * NW + in * 8 + gid;
                uint32_t bh0 = Bsh[br * STR + ac];
                uint32_t bh1 = Bsh[br * STR + ac + 4];
                uint32_t bl0 = Bsl[br * STR + ac];
                uint32_t bl1 = Bsl[br * STR + ac + 4];
#pragma unroll
                for (int im = 0; im < MAT; im++) {
                    asm volatile(
                        "mma.sync.aligned.m16n8k8.row.col.f32.tf32.tf32.f32 "
                        "{%0,%1,%2,%3}, {%4,%5,%6,%7}, {%8,%9}, {%0,%1,%2,%3};"
                        : "+f"(acc[im][in][0]), "+f"(acc[im][in][1]),
                          "+f"(acc[im][in][2]), "+f"(acc[im][in][3])
                        : "r"(al[im][0]), "r"(al[im][1]), "r"(al[im][2]), "r"(al[im][3]),
                          "r"(bh0), "r"(bh1));
                    asm volatile(
                        "mma.sync.aligned.m16n8k8.row.col.f32.tf32.tf32.f32 "
                        "{%0,%1,%2,%3}, {%4,%5,%6,%7}, {%8,%9}, {%0,%1,%2,%3};"
                        : "+f"(acc[im][in][0]), "+f"(acc[im][in][1]),
                          "+f"(acc[im][in][2]), "+f"(acc[im][in][3])
                        : "r"(ah[im][0]), "r"(ah[im][1]), "r"(ah[im][2]), "r"(ah[im][3]),
                          "r"(bl0), "r"(bl1));
                    asm volatile(
                        "mma.sync.aligned.m16n8k8.row.col.f32.tf32.tf32.f32 "
                        "{%0,%1,%2,%3}, {%4,%5,%6,%7}, {%8,%9}, {%0,%1,%2,%3};"
                        : "+f"(acc[im][in][0]), "+f"(acc[im][in][1]),
                          "+f"(acc[im][in][2]), "+f"(acc[im][in][3])
                        : "r"(ah[im][0]), "r"(ah[im][1]), "r"(ah[im][2]), "r"(ah[im][3]),
                          "r"(bh0), "r"(bh1));
                }
            }
        }
        __syncthreads();
    }

    // ---- epilogue ----
#pragma unroll
    for (int im = 0; im < MAT; im++) {
        int r0 = m0 + wm * MW + im * 16 + gid;
        int r1 = r0 + 8;
#pragma unroll
        for (int in = 0; in < NAT; in++) {
            int cc = n0 + wn * NW + in * 8 + tig * 2;
            float v0 = acc[im][in][0], v1 = acc[im][in][1];
            float v2 = acc[im][in][2], v3 = acc[im][in][3];
            if (C2) {
                float2 b2 = *(const float2*)&bias2[cc];
                if (r0 < M) *(float2*)&C2[(long long)r0 * N + cc] = make_float2(v0 + b2.x, v1 + b2.y);
                if (r1 < M) *(float2*)&C2[(long long)r1 * N + cc] = make_float2(v2 + b2.x, v3 + b2.y);
            }
            if (bias) {
                float2 bv = *(const float2*)&bias[cc];
                v0 += bv.x; v1 += bv.y; v2 += bv.x; v3 += bv.y;
            }
            if (reluOut) {
                v0 = fmaxf(v0, 0.f); v1 = fmaxf(v1, 0.f);
                v2 = fmaxf(v2, 0.f); v3 = fmaxf(v3, 0.f);
            }
            if (r0 < M) *(float2*)&C[(long long)r0 * N + cc] = make_float2(v0, v1);
            if (r1 < M) *(float2*)&C[(long long)r1 * N + cc] = make_float2(v2, v3);
        }
    }
}

// ---------------- edge scatter: A[dst] += Y[src], MLP=2 per thread ----------------
__global__ void scatter_add(const float* __restrict__ Y, float* __restrict__ A,
                            const void* __restrict__ eidx, int E, int C4) {
    const int is64 = g_is64;
    long long total = (long long)E * C4;
    long long half = (total + 1) >> 1;
    long long i0 = (long long)blockIdx.x * blockDim.x + threadIdx.x;
    if (i0 >= half) return;
    long long i1 = i0 + half;
    const int C = C4 * 4;

    int e0 = (int)(i0 / C4), c0 = (int)(i0 % C4) * 4;
    int src0 = load_idx(eidx, e0, is64);
    int dst0 = load_idx(eidx, (long long)E + e0, is64);
    float4 v0 = *(const float4*)&Y[(long long)src0 * C + c0];

    bool has1 = (i1 < total);
    int e1 = 0, c1 = 0, src1 = 0, dst1 = 0;
    float4 v1 = make_float4(0.f, 0.f, 0.f, 0.f);
    if (has1) {
        e1 = (int)(i1 / C4); c1 = (int)(i1 % C4) * 4;
        src1 = load_idx(eidx, e1, is64);
        dst1 = load_idx(eidx, (long long)E + e1, is64);
        v1 = *(const float4*)&Y[(long long)src1 * C + c1];
    }

    float* p0 = &A[(long long)dst0 * C + c0];
    asm volatile("red.global.add.v4.f32 [%0], {%1, %2, %3, %4};"
                 :: "l"(p0), "f"(v0.x), "f"(v0.y), "f"(v0.z), "f"(v0.w) : "memory");
    if (has1) {
        float* p1 = &A[(long long)dst1 * C + c1];
        asm volatile("red.global.add.v4.f32 [%0], {%1, %2, %3, %4};"
                     :: "l"(p1), "f"(v1.x), "f"(v1.y), "f"(v1.z), "f"(v1.w) : "memory");
    }
}

// ---------------- batchnorm statistics (standalone, proven) ----------------
__global__ void zero_f(float* __restrict__ p, int n) {
    int i = blockIdx.x * blockDim.x + threadIdx.x;
    if (i < n) p[i] = 0.f;
}

__global__ void col_stats(const float* __restrict__ H, int M, int C) {
    const int c = threadIdx.x;            // blockDim.x == C
    const int r0 = blockIdx.x * 256;
    const int r1 = min(r0 + 256, M);
    float s = 0.f, q = 0.f;
    for (int r = r0; r < r1; ++r) {
        float v = H[(long long)r * C + c];
        s += v;
        q = fmaf(v, v, q);
    }
    atomicAdd(&g_stats[c], s);
    atomicAdd(&g_stats[256 + c], q);
}

// ---------------- pooling (applies BN3 inline) + head ----------------
__global__ void pool_bn_add(const float* __restrict__ H, float* __restrict__ P,
                            const void* __restrict__ batch,
                            const float* __restrict__ coef, int M) {
    const int is64 = g_is64;
    long long i = (long long)blockIdx.x * blockDim.x + threadIdx.x;
    long long total = (long long)M * 16;      // C=64 -> 16 float4 per node
    if (i >= total) return;
    int node = (int)(i / 16);
    int c = (int)(i % 16) * 4;
    int gph = load_idx(batch, node, is64);
    float4 v = *(const float4*)&H[(long long)node * 64 + c];
    float4 s = *(const float4*)&coef[c];
    float4 t = *(const float4*)&coef[256 + c];
    v.x = fmaf(v.x, s.x, t.x); v.y = fmaf(v.y, s.y, t.y);
    v.z = fmaf(v.z, s.z, t.z); v.w = fmaf(v.w, s.w, t.w);
    float* p = &P[(long long)gph * 64 + c];
    asm volatile("red.global.add.v4.f32 [%0], {%1, %2, %3, %4};"
                 :: "l"(p), "f"(v.x), "f"(v.y), "f"(v.z), "f"(v.w) : "memory");
}

__global__ void head_kernel(const float* __restrict__ P,
                            const float* __restrict__ Wf1, const float* __restrict__ bf1,
                            const float* __restrict__ Wf2, const float* __restrict__ bf2,
                            float* __restrict__ out, int G) {
    int g = blockIdx.x * blockDim.x + threadIdx.x;
    if (g >= G) return;
    float acc[16];
#pragma unroll
    for (int j = 0; j < 16; j++) acc[j] = bf1[j];
    const float* p = &P[(long long)g * 64];
    for (int k = 0; k < 64; k++) {
        float pv = p[k];
#pragma unroll
        for (int j = 0; j < 16; j++) acc[j] = fmaf(pv, Wf1[k * 16 + j], acc[j]);
    }
    float o = bf2[0];
#pragma unroll
    for (int j = 0; j < 16; j++) o = fmaf(fmaxf(acc[j], 0.f), Wf2[j], o);
    out[g] = fmaxf(o, 0.f);
}

// ---------------- host launcher ----------------
static void launch_transpose(const float* W, uint32_t* BtHi, uint32_t* BtLo,
                             int K, int N, const float* scale) {
    dim3 grid((N + 31) / 32, (K + 31) / 32);
    transpose_w_split<<<grid, dim3(32, 8)>>>(W, BtHi, BtLo, K, N, scale);
}

static void launch_scatter(const float* Y, float* A, const void* eidx, int E, int C4) {
    long long total = (long long)E * C4;
    long long half = (total + 1) >> 1;
    scatter_add<<<(int)((half + 255) / 256), 256>>>(Y, A, eidx, E, C4);
}

template <int BN_, int WM_, int WN_, int RELUIN, int VEC4>
static void launch_gemm(const float* A, const uint32_t* BtHi, const uint32_t* BtLo,
                        float* C, int M, int N, int K, const float* bias,
                        int reluOut, float* C2, const float* bias2) {
    constexpr int SMEM_BYTES = (2 * 128 + 4 * BN_) * 36 * 4;
    static bool attr_set = false;
    if (!attr_set) {
        cudaFuncSetAttribute(mma_gemm<BN_, WM_, WN_, RELUIN, VEC4>,
                             cudaFuncAttributeMaxDynamicSharedMemorySize, SMEM_BYTES);
        attr_set = true;
    }
    dim3 grid(N / BN_, (M + 127) / 128);
    mma_gemm<BN_, WM_, WN_, RELUIN, VEC4><<<grid, 256, SMEM_BYTES>>>(
        A, BtHi, BtLo, C, M, N, K, bias, reluOut, C2, bias2);
}

extern "C" void kernel_launch(void* const* d_in, const int* in_sizes, int n_in,
                              void* d_out, int out_size) {
    const float* x    = (const float*)d_in[0];
    const void*  eidx = d_in[1];
    const void*  batc = d_in[2];
    const float* W1a = (const float*)d_in[3];  const float* b1a = (const float*)d_in[4];
    const float* W1b = (const float*)d_in[5];  const float* b1b = (const float*)d_in[6];
    const float* g1  = (const float*)d_in[7];  const float* be1 = (const float*)d_in[8];
    const float* W2a = (const float*)d_in[9];  const float* b2a = (const float*)d_in[10];
    const float* W2b = (const float*)d_in[11]; const float* b2b = (const float*)d_in[12];
    const float* g2  = (const float*)d_in[13]; const float* be2 = (const float*)d_in[14];
    const float* W3a = (const float*)d_in[15]; const float* b3a = (const float*)d_in[16];
    const float* W3b = (const float*)d_in[17]; const float* b3b = (const float*)d_in[18];
    const float* g3  = (const float*)d_in[19]; const float* be3 = (const float*)d_in[20];
    const float* Wf1 = (const float*)d_in[21]; const float* bf1 = (const float*)d_in[22];
    const float* Wf2 = (const float*)d_in[23]; const float* bf2 = (const float*)d_in[24];

    float *Y, *A, *H1, *H2, *H3, *P, *ST, *CF, *BY, *BA;
    uint32_t *BH, *BL;
    cudaGetSymbolAddress((void**)&Y,  g_Y);
    cudaGetSymbolAddress((void**)&A,  g_A);
    cudaGetSymbolAddress((void**)&H1, g_H1);
    cudaGetSymbolAddress((void**)&H2, g_H2);
    cudaGetSymbolAddress((void**)&H3, g_H3);
    cudaGetSymbolAddress((void**)&P,  g_pool);
    cudaGetSymbolAddress((void**)&ST, g_stats);
    cudaGetSymbolAddress((void**)&CF, g_coef);
    cudaGetSymbolAddress((void**)&BY, g_biasY);
    cudaGetSymbolAddress((void**)&BA, g_biasA);
    cudaGetSymbolAddress((void**)&BH, g_BtHi);
    cudaGetSymbolAddress((void**)&BL, g_BtLo);

    detect_dtype<<<1, 256>>>((const unsigned int*)eidx, 1024);

    const int M = NN;

    // ---- Layer 1: 373 -> 256 (no BN on input; K=373 -> scalar staging) ----
    launch_transpose(W1a, BH, BL, 373, 256, nullptr);
    launch_gemm<128, 2, 4, 0, 0>(x, BH, BL, Y, M, 256, 373, nullptr, 0, A, b1a);
    launch_scatter(Y, A, eidx, NE, 64);
    launch_transpose(W1b, BH, BL, 256, 256, nullptr);
    launch_gemm<128, 2, 4, 1, 1>(A, BH, BL, H1, M, 256, 256, b1b, 1, nullptr, nullptr);
    col_stats<<<(M + 255) / 256, 256>>>(H1, M, 256);
    bn_coef<<<1, 512>>>(256, g1, be1, ST, CF);

    // ---- Layer 2: 256 -> 128 (BN1 folded into W2a) ----
    launch_transpose(W2a, BH, BL, 256, 128, CF);
    vecmat_bias<<<1, 128>>>(W2a, CF, b2a, BY, BA, 256, 128);
    launch_gemm<128, 2, 4, 0, 1>(H1, BH, BL, Y, M, 128, 256, BY, 0, A, BA);
    launch_scatter(Y, A, eidx, NE, 32);
    launch_transpose(W2b, BH, BL, 128, 128, nullptr);
    launch_gemm<128, 2, 4, 1, 1>(A, BH, BL, H2, M, 128, 128, b2b, 1, nullptr, nullptr);
    col_stats<<<(M + 255) / 256, 128>>>(H2, M, 128);
    bn_coef<<<1, 512>>>(128, g2, be2, ST, CF);

    // ---- Layer 3: 128 -> 64 (BN2 folded into W3a) ----
    launch_transpose(W3a, BH, BL, 128, 64, CF);
    vecmat_bias<<<1, 64>>>(W3a, CF, b3a, BY, BA, 128, 64);
    launch_gemm<64, 4, 2, 0, 1>(H2, BH, BL, Y, M, 64, 128, BY, 0, A, BA);
    launch_scatter(Y, A, eidx, NE, 16);
    launch_transpose(W3b, BH, BL, 64, 64, nullptr);
    launch_gemm<64, 4, 2, 1, 1>(A, BH, BL, H3, M, 64, 64, b3b, 1, nullptr, nullptr);
    col_stats<<<(M + 255) / 256, 64>>>(H3, M, 64);
    bn_coef<<<1, 512>>>(64, g3, be3, ST, CF);

    // ---- Pool (BN3 inline) + head ----
    zero_f<<<(NG * 64 + 255) / 256, 256>>>(P, NG * 64);
    {
        long long tot = (long long)M * 16;
        pool_bn_add<<<(int)((tot + 255) / 256), 256>>>(H3, P, batc, CF, M);
    }
    head_kernel<<<(NG + 127) / 128, 128>>>(P, Wf1, bf1, Wf2, bf2, (float*)d_out, NG);
}

// round 15
// speedup vs baseline: 1.3966x; 1.3966x over previous
#include <cuda_runtime.h>
#include <cuda_bf16.h>
#include <cstdint>

#define NN 100000
#define NE 400000
#define NG 4096
#define BN_EPS 1e-5f

// ---------------- scratch (device globals; no allocations allowed) ----------------
__device__ float g_Y[NN * 256];        // projection output
__device__ float g_A[NN * 256];        // self + bias + aggregated neighbors
__device__ float g_H1[NN * 256];
__device__ float g_H2[NN * 128];
__device__ float g_H3[NN * 64];
__device__ float g_pool[NG * 64];
__device__ float g_stats[512];         // [0:256) col sums, [256:512) col sumsq (zero at rest)
__device__ float g_coef[512];          // [0:256) scale s, [256:512) shift t
__device__ float g_biasY[256];         // t @ W  (per-N bias for Y output)
__device__ float g_biasA[256];         // t @ W + b (per-N bias for A output)
__device__ float g_Bt[373 * 256];      // transposed (optionally row-scaled) weight [N,K]
__device__ int   g_is64;

// ---------------- dtype detection (int64 vs int32 indices) ----------------
__global__ void detect_dtype(const unsigned int* __restrict__ w, int n) {
    __shared__ int anyNZ;
    if (threadIdx.x == 0) anyNZ = 0;
    __syncthreads();
    for (int i = threadIdx.x; i < n; i += blockDim.x)
        if (w[2 * i + 1] != 0u) anyNZ = 1;
    __syncthreads();
    if (threadIdx.x == 0) g_is64 = (anyNZ == 0) ? 1 : 0;
}

__device__ __forceinline__ int load_idx(const void* p, long long i, int is64) {
    return is64 ? (int)((const long long*)p)[i] : ((const int*)p)[i];
}

// Split two fp32 values into packed bf16x2 hi + bf16x2 lo (hi.lo16 = v0).
__device__ __forceinline__ void split_bf16x2(float v0, float v1, uint32_t& hi, uint32_t& lo) {
    asm("cvt.rn.bf16x2.f32 %0, %1, %2;" : "=r"(hi) : "f"(v1), "f"(v0));
    float h0 = __uint_as_float(hi << 16);
    float h1 = __uint_as_float(hi & 0xFFFF0000u);
    float r0 = v0 - h0;
    float r1 = v1 - h1;
    asm("cvt.rn.bf16x2.f32 %0, %1, %2;" : "=r"(lo) : "f"(r1), "f"(r0));
}

__device__ __forceinline__ void cp4(uint32_t dst, const void* src, bool valid) {
    int sz = valid ? 4 : 0;
    asm volatile("cp.async.ca.shared.global [%0], [%1], 4, %2;"
                 :: "r"(dst), "l"(src), "r"(sz) : "memory");
}

__device__ __forceinline__ void cp16(uint32_t dst, const void* src, bool valid) {
    int sz = valid ? 16 : 0;
    asm volatile("cp.async.ca.shared.global [%0], [%1], 16, %2;"
                 :: "r"(dst), "l"(src), "r"(sz) : "memory");
}

// ---------------- weight transpose: [K,N] -> [N,K], optional per-K row scale ----------------
__global__ void transpose_w(const float* __restrict__ in, float* __restrict__ out,
                            int K, int N, const float* __restrict__ scale) {
    __shared__ float t[32][33];
    int kx = blockIdx.y * 32, nx = blockIdx.x * 32;
    int x = threadIdx.x, y = threadIdx.y;      // 32 x 8
#pragma unroll
    for (int j = 0; j < 32; j += 8) {
        int k = kx + y + j, n = nx + x;
        float v = 0.f;
        if (k < K && n < N) {
            v = in[(long long)k * N + n];
            if (scale) v *= scale[k];
        }
        t[y + j][x] = v;
    }
    __syncthreads();
#pragma unroll
    for (int j = 0; j < 32; j += 8) {
        int n = nx + y + j, k = kx + x;
        if (n < N && k < K) out[(long long)n * K + k] = t[x][y + j];
    }
}

// ---------------- bias correction: BY[n] = t @ W[:,n]; BA[n] = BY[n] + b[n] ----------------
__global__ void vecmat_bias(const float* __restrict__ W, const float* __restrict__ coef,
                            const float* __restrict__ b,
                            float* __restrict__ BY, float* __restrict__ BA,
                            int K, int N) {
    int n = blockIdx.x * blockDim.x + threadIdx.x;
    if (n >= N) return;
    float s = 0.f;
    for (int k = 0; k < K; k++)
        s = fmaf(coef[256 + k], W[(long long)k * N + n], s);
    BY[n] = s;
    BA[n] = s + b[n];
}

// ---------------- BN coefficients from stats (race-free; re-zero for replay) ----------------
__global__ void bn_coef(int C, const float* __restrict__ g, const float* __restrict__ be,
                        float* __restrict__ stats, float* __restrict__ coef) {
    int c = threadIdx.x;   // 512 threads
    float sum = 0.f, sq = 0.f;
    if (c < C) {
        sum = stats[c];
        sq  = stats[256 + c];           // read BEFORE anyone zeroes
    }
    __syncthreads();                    // all reads complete before zeroing
    stats[c] = 0.f;
    if (c < C) {
        float invN = 1.f / (float)NN;
        float mu = sum * invN;
        float var = fmaf(-mu, mu, sq * invN);
        float s = rsqrtf(var + BN_EPS) * g[c];
        coef[c] = s;
        coef[256 + c] = fmaf(-mu, s, be[c]);
    }
}

// ---------------- 3xBF16 mma.sync GEMM (m16n8k16), cp.async double-buffered, 2 CTAs/SM ----
// C[M,N] = f(A[M,K]) @ Bt[N,K]^T  (f = relu if RELUIN, applied at fragment load)
// Emulated fp32 via bf16 hi/lo split: acc += a_lo*b_hi + a_hi*b_lo + a_hi*b_hi.
// epilogue: C = (acc + bias) [relu]; optional C2 = acc + bias2.
// VEC4: 16-byte cp.async staging (requires K % 32 == 0).
template <int BN_, int WM_, int WN_, int RELUIN, int VEC4>
__global__ __launch_bounds__(256, 2)
void mma_gemm(const float* __restrict__ A, const float* __restrict__ Bt,
              float* __restrict__ C, int M, int N, int K,
              const float* __restrict__ bias, int reluOut,
              float* __restrict__ C2, const float* __restrict__ bias2) {
    constexpr int BM = 128, BK = 32, STR = 36;
    constexpr int MW = BM / WM_;
    constexpr int NW = BN_ / WN_;
    constexpr int MAT = MW / 16;
    constexpr int NAT = NW / 8;
    extern __shared__ float smem[];
    uint32_t smem_u32;
    asm("{ .reg .u64 t; cvta.to.shared.u64 t, %1; cvt.u32.u64 %0, t; }"
        : "=r"(smem_u32) : "l"(smem));

    const int tid = threadIdx.x;
    const int wid = tid >> 5, lane = tid & 31;
    const int gid = lane >> 2, tig = lane & 3;
    const int wm = wid / WN_, wn = wid % WN_;
    const int m0 = blockIdx.y * BM;
    const int n0 = blockIdx.x * BN_;

    float acc[MAT][NAT][4];
#pragma unroll
    for (int i = 0; i < MAT; i++)
#pragma unroll
        for (int j = 0; j < NAT; j++)
#pragma unroll
            for (int q = 0; q < 4; q++) acc[i][j][q] = 0.f;

    const int KT = (K + BK - 1) / BK;

    auto stage = [&](int kt, int b) {
        const int k0 = kt * BK;
        if (VEC4) {
#pragma unroll
            for (int it = 0; it < (BM * 8) / 256; ++it) {
                int i = tid + it * 256;
                int row = i >> 3, c4 = (i & 7) * 4;
                int gm = m0 + row, gk = k0 + c4;
                bool ok = (gm < M);
                long long gi = ok ? ((long long)gm * K + gk) : 0;
                uint32_t d = smem_u32 + (uint32_t)((b * BM * STR + row * STR + c4) * 4);
                cp16(d, A + gi, ok);
            }
#pragma unroll
            for (int it = 0; it < (BN_ * 8) / 256; ++it) {
                int i = tid + it * 256;
                int n = i >> 3, c4 = (i & 7) * 4;
                int gn = n0 + n, gk = k0 + c4;
                bool ok = (gn < N);
                long long gi = ok ? ((long long)gn * K + gk) : 0;
                uint32_t d = smem_u32 + (uint32_t)(((2 * BM + b * BN_) * STR + n * STR + c4) * 4);
                cp16(d, Bt + gi, ok);
            }
        } else {
#pragma unroll
            for (int it = 0; it < (BM * BK) / 256; ++it) {
                int i = tid + it * 256;
                int row = i >> 5, col = i & 31;
                int gm = m0 + row, gk = k0 + col;
                bool ok = (gm < M) && (gk < K);
                long long gi = ok ? ((long long)gm * K + gk) : 0;
                uint32_t d = smem_u32 + (uint32_t)((b * BM * STR + row * STR + col) * 4);
                cp4(d, A + gi, ok);
            }
#pragma unroll
            for (int it = 0; it < (BN_ * BK) / 256; ++it) {
                int i = tid + it * 256;
                int n = i >> 5, col = i & 31;
                int gn = n0 + n, gk = k0 + col;
                bool ok = (gn < N) && (gk < K);
                long long gi = ok ? ((long long)gn * K + gk) : 0;
                uint32_t d = smem_u32 + (uint32_t)(((2 * BM + b * BN_) * STR + n * STR + col) * 4);
                cp4(d, Bt + gi, ok);
            }
        }
        asm volatile("cp.async.commit_group;" ::: "memory");
    };

    stage(0, 0);
    for (int kt = 0; kt < KT; ++kt) {
        if (kt + 1 < KT) {
            stage(kt + 1, (kt + 1) & 1);
            asm volatile("cp.async.wait_group 1;" ::: "memory");
        } else {
            asm volatile("cp.async.wait_group 0;" ::: "memory");
        }
        __syncthreads();

        const float* As = smem + (kt & 1) * BM * STR;
        const float* Bs = smem + (2 * BM + (kt & 1) * BN_) * STR;

#pragma unroll
        for (int ks = 0; ks < 2; ks++) {          // two K=16 mma steps per 32-K tile
            const int kb = ks * 16 + tig * 2;     // this thread's low k-pair base
            uint32_t ah[MAT][4], al[MAT][4];
#pragma unroll
            for (int im = 0; im < MAT; im++) {
                int ar = wm * MW + im * 16 + gid;
                float2 v00 = *(const float2*)&As[ar * STR + kb];
                float2 v10 = *(const float2*)&As[(ar + 8) * STR + kb];
                float2 v01 = *(const float2*)&As[ar * STR + kb + 8];
                float2 v11 = *(const float2*)&As[(ar + 8) * STR + kb + 8];
                if (RELUIN) {
                    v00.x = fmaxf(v00.x, 0.f); v00.y = fmaxf(v00.y, 0.f);
                    v10.x = fmaxf(v10.x, 0.f); v10.y = fmaxf(v10.y, 0.f);
                    v01.x = fmaxf(v01.x, 0.f); v01.y = fmaxf(v01.y, 0.f);
                    v11.x = fmaxf(v11.x, 0.f); v11.y = fmaxf(v11.y, 0.f);
                }
                split_bf16x2(v00.x, v00.y, ah[im][0], al[im][0]);
                split_bf16x2(v10.x, v10.y, ah[im][1], al[im][1]);
                split_bf16x2(v01.x, v01.y, ah[im][2], al[im][2]);
                split_bf16x2(v11.x, v11.y, ah[im][3], al[im][3]);
            }
#pragma unroll
            for (int in = 0; in < NAT; in++) {
                int br = wn * NW + in * 8 + gid;
                float2 w0 = *(const float2*)&Bs[br * STR + kb];
                float2 w1 = *(const float2*)&Bs[br * STR + kb + 8];
                uint32_t bh0, bl0, bh1, bl1;
                split_bf16x2(w0.x, w0.y, bh0, bl0);
                split_bf16x2(w1.x, w1.y, bh1, bl1);
#pragma unroll
                for (int im = 0; im < MAT; im++) {
                    asm volatile(
                        "mma.sync.aligned.m16n8k16.row.col.f32.bf16.bf16.f32 "
                        "{%0,%1,%2,%3}, {%4,%5,%6,%7}, {%8,%9}, {%0,%1,%2,%3};"
                        : "+f"(acc[im][in][0]), "+f"(acc[im][in][1]),
                          "+f"(acc[im][in][2]), "+f"(acc[im][in][3])
                        : "r"(al[im][0]), "r"(al[im][1]), "r"(al[im][2]), "r"(al[im][3]),
                          "r"(bh0), "r"(bh1));
                    asm volatile(
                        "mma.sync.aligned.m16n8k16.row.col.f32.bf16.bf16.f32 "
                        "{%0,%1,%2,%3}, {%4,%5,%6,%7}, {%8,%9}, {%0,%1,%2,%3};"
                        : "+f"(acc[im][in][0]), "+f"(acc[im][in][1]),
                          "+f"(acc[im][in][2]), "+f"(acc[im][in][3])
                        : "r"(ah[im][0]), "r"(ah[im][1]), "r"(ah[im][2]), "r"(ah[im][3]),
                          "r"(bl0), "r"(bl1));
                    asm volatile(
                        "mma.sync.aligned.m16n8k16.row.col.f32.bf16.bf16.f32 "
                        "{%0,%1,%2,%3}, {%4,%5,%6,%7}, {%8,%9}, {%0,%1,%2,%3};"
                        : "+f"(acc[im][in][0]), "+f"(acc[im][in][1]),
                          "+f"(acc[im][in][2]), "+f"(acc[im][in][3])
                        : "r"(ah[im][0]), "r"(ah[im][1]), "r"(ah[im][2]), "r"(ah[im][3]),
                          "r"(bh0), "r"(bh1));
                }
            }
        }
        __syncthreads();
    }

    // ---- epilogue (C layout of m16n8k16 == m16n8k8) ----
#pragma unroll
    for (int im = 0; im < MAT; im++) {
        int r0 = m0 + wm * MW + im * 16 + gid;
        int r1 = r0 + 8;
#pragma unroll
        for (int in = 0; in < NAT; in++) {
            int cc = n0 + wn * NW + in * 8 + tig * 2;
            float v0 = acc[im][in][0], v1 = acc[im][in][1];
            float v2 = acc[im][in][2], v3 = acc[im][in][3];
            if (C2) {
                float2 b2 = *(const float2*)&bias2[cc];
                if (r0 < M) *(float2*)&C2[(long long)r0 * N + cc] = make_float2(v0 + b2.x, v1 + b2.y);
                if (r1 < M) *(float2*)&C2[(long long)r1 * N + cc] = make_float2(v2 + b2.x, v3 + b2.y);
            }
            if (bias) {
                float2 bv = *(const float2*)&bias[cc];
                v0 += bv.x; v1 += bv.y; v2 += bv.x; v3 += bv.y;
            }
            if (reluOut) {
                v0 = fmaxf(v0, 0.f); v1 = fmaxf(v1, 0.f);
                v2 = fmaxf(v2, 0.f); v3 = fmaxf(v3, 0.f);
            }
            if (r0 < M) *(float2*)&C[(long long)r0 * N + cc] = make_float2(v0, v1);
            if (r1 < M) *(float2*)&C[(long long)r1 * N + cc] = make_float2(v2, v3);
        }
    }
}

// ---------------- edge scatter: A[dst] += Y[src], MLP=2 per thread ----------------
__global__ void scatter_add(const float* __restrict__ Y, float* __restrict__ A,
                            const void* __restrict__ eidx, int E, int C4) {
    const int is64 = g_is64;
    long long total = (long long)E * C4;
    long long half = (total + 1) >> 1;
    long long i0 = (long long)blockIdx.x * blockDim.x + threadIdx.x;
    if (i0 >= half) return;
    long long i1 = i0 + half;
    const int C = C4 * 4;

    int e0 = (int)(i0 / C4), c0 = (int)(i0 % C4) * 4;
    int src0 = load_idx(eidx, e0, is64);
    int dst0 = load_idx(eidx, (long long)E + e0, is64);
    float4 v0 = *(const float4*)&Y[(long long)src0 * C + c0];

    bool has1 = (i1 < total);
    int e1 = 0, c1 = 0, src1 = 0, dst1 = 0;
    float4 v1 = make_float4(0.f, 0.f, 0.f, 0.f);
    if (has1) {
        e1 = (int)(i1 / C4); c1 = (int)(i1 % C4) * 4;
        src1 = load_idx(eidx, e1, is64);
        dst1 = load_idx(eidx, (long long)E + e1, is64);
        v1 = *(const float4*)&Y[(long long)src1 * C + c1];
    }

    float* p0 = &A[(long long)dst0 * C + c0];
    asm volatile("red.global.add.v4.f32 [%0], {%1, %2, %3, %4};"
                 :: "l"(p0), "f"(v0.x), "f"(v0.y), "f"(v0.z), "f"(v0.w) : "memory");
    if (has1) {
        float* p1 = &A[(long long)dst1 * C + c1];
        asm volatile("red.global.add.v4.f32 [%0], {%1, %2, %3, %4};"
                     :: "l"(p1), "f"(v1.x), "f"(v1.y), "f"(v1.z), "f"(v1.w) : "memory");
    }
}

// ---------------- batchnorm statistics (standalone, proven) ----------------
__global__ void zero_f(float* __restrict__ p, int n) {
    int i = blockIdx.x * blockDim.x + threadIdx.x;
    if (i < n) p[i] = 0.f;
}

__global__ void col_stats(const float* __restrict__ H, int M, int C) {
    const int c = threadIdx.x;            // blockDim.x == C
    const int r0 = blockIdx.x * 256;
    const int r1 = min(r0 + 256, M);
    float s = 0.f, q = 0.f;
    for (int r = r0; r < r1; ++r) {
        float v = H[(long long)r * C + c];
        s += v;
        q = fmaf(v, v, q);
    }
    atomicAdd(&g_stats[c], s);
    atomicAdd(&g_stats[256 + c], q);
}

// ---------------- pooling (applies BN3 inline) + head ----------------
__global__ void pool_bn_add(const float* __restrict__ H, float* __restrict__ P,
                            const void* __restrict__ batch,
                            const float* __restrict__ coef, int M) {
    const int is64 = g_is64;
    long long i = (long long)blockIdx.x * blockDim.x + threadIdx.x;
    long long total = (long long)M * 16;      // C=64 -> 16 float4 per node
    if (i >= total) return;
    int node = (int)(i / 16);
    int c = (int)(i % 16) * 4;
    int gph = load_idx(batch, node, is64);
    float4 v = *(const float4*)&H[(long long)node * 64 + c];
    float4 s = *(const float4*)&coef[c];
    float4 t = *(const float4*)&coef[256 + c];
    v.x = fmaf(v.x, s.x, t.x); v.y = fmaf(v.y, s.y, t.y);
    v.z = fmaf(v.z, s.z, t.z); v.w = fmaf(v.w, s.w, t.w);
    float* p = &P[(long long)gph * 64 + c];
    asm volatile("red.global.add.v4.f32 [%0], {%1, %2, %3, %4};"
                 :: "l"(p), "f"(v.x), "f"(v.y), "f"(v.z), "f"(v.w) : "memory");
}

__global__ void head_kernel(const float* __restrict__ P,
                            const float* __restrict__ Wf1, const float* __restrict__ bf1,
                            const float* __restrict__ Wf2, const float* __restrict__ bf2,
                            float* __restrict__ out, int G) {
    int g = blockIdx.x * blockDim.x + threadIdx.x;
    if (g >= G) return;
    float acc[16];
#pragma unroll
    for (int j = 0; j < 16; j++) acc[j] = bf1[j];
    const float* p = &P[(long long)g * 64];
    for (int k = 0; k < 64; k++) {
        float pv = p[k];
#pragma unroll
        for (int j = 0; j < 16; j++) acc[j] = fmaf(pv, Wf1[k * 16 + j], acc[j]);
    }
    float o = bf2[0];
#pragma unroll
    for (int j = 0; j < 16; j++) o = fmaf(fmaxf(acc[j], 0.f), Wf2[j], o);
    out[g] = fmaxf(o, 0.f);
}

// ---------------- host launcher ----------------
static void launch_transpose(const float* W, float* Bt, int K, int N, const float* scale) {
    dim3 grid((N + 31) / 32, (K + 31) / 32);
    transpose_w<<<grid, dim3(32, 8)>>>(W, Bt, K, N, scale);
}

static void launch_scatter(const float* Y, float* A, const void* eidx, int E, int C4) {
    long long total = (long long)E * C4;
    long long half = (total + 1) >> 1;
    scatter_add<<<(int)((half + 255) / 256), 256>>>(Y, A, eidx, E, C4);
}

template <int BN_, int WM_, int WN_, int RELUIN, int VEC4>
static void launch_gemm(const float* A, const float* Bt, float* C,
                        int M, int N, int K, const float* bias,
                        int reluOut, float* C2, const float* bias2) {
    constexpr int SMEM_BYTES = (2 * 128 + 2 * BN_) * 36 * 4;
    static bool attr_set = false;
    if (!attr_set) {
        cudaFuncSetAttribute(mma_gemm<BN_, WM_, WN_, RELUIN, VEC4>,
                             cudaFuncAttributeMaxDynamicSharedMemorySize, SMEM_BYTES);
        attr_set = true;
    }
    dim3 grid(N / BN_, (M + 127) / 128);
    mma_gemm<BN_, WM_, WN_, RELUIN, VEC4><<<grid, 256, SMEM_BYTES>>>(
        A, Bt, C, M, N, K, bias, reluOut, C2, bias2);
}

extern "C" void kernel_launch(void* const* d_in, const int* in_sizes, int n_in,
                              void* d_out, int out_size) {
    const float* x    = (const float*)d_in[0];
    const void*  eidx = d_in[1];
    const void*  batc = d_in[2];
    const float* W1a = (const float*)d_in[3];  const float* b1a = (const float*)d_in[4];
    const float* W1b = (const float*)d_in[5];  const float* b1b = (const float*)d_in[6];
    const float* g1  = (const float*)d_in[7];  const float* be1 = (const float*)d_in[8];
    const float* W2a = (const float*)d_in[9];  const float* b2a = (const float*)d_in[10];
    const float* W2b = (const float*)d_in[11]; const float* b2b = (const float*)d_in[12];
    const float* g2  = (const float*)d_in[13]; const float* be2 = (const float*)d_in[14];
    const float* W3a = (const float*)d_in[15]; const float* b3a = (const float*)d_in[16];
    const float* W3b = (const float*)d_in[17]; const float* b3b = (const float*)d_in[18];
    const float* g3  = (const float*)d_in[19]; const float* be3 = (const float*)d_in[20];
    const float* Wf1 = (const float*)d_in[21]; const float* bf1 = (const float*)d_in[22];
    const float* Wf2 = (const float*)d_in[23]; const float* bf2 = (const float*)d_in[24];

    float *Y, *A, *H1, *H2, *H3, *P, *ST, *CF, *BY, *BA, *BT;
    cudaGetSymbolAddress((void**)&Y,  g_Y);
    cudaGetSymbolAddress((void**)&A,  g_A);
    cudaGetSymbolAddress((void**)&H1, g_H1);
    cudaGetSymbolAddress((void**)&H2, g_H2);
    cudaGetSymbolAddress((void**)&H3, g_H3);
    cudaGetSymbolAddress((void**)&P,  g_pool);
    cudaGetSymbolAddress((void**)&ST, g_stats);
    cudaGetSymbolAddress((void**)&CF, g_coef);
    cudaGetSymbolAddress((void**)&BY, g_biasY);
    cudaGetSymbolAddress((void**)&BA, g_biasA);
    cudaGetSymbolAddress((void**)&BT, g_Bt);

    detect_dtype<<<1, 256>>>((const unsigned int*)eidx, 1024);

    const int M = NN;

    // ---- Layer 1: 373 -> 256 (no BN on input; K=373 -> scalar staging) ----
    launch_transpose(W1a, BT, 373, 256, nullptr);
    launch_gemm<128, 2, 4, 0, 0>(x, BT, Y, M, 256, 373, nullptr, 0, A, b1a);
    launch_scatter(Y, A, eidx, NE, 64);
    launch_transpose(W1b, BT, 256, 256, nullptr);
    launch_gemm<128, 2, 4, 1, 1>(A, BT, H1, M, 256, 256, b1b, 1, nullptr, nullptr);
    col_stats<<<(M + 255) / 256, 256>>>(H1, M, 256);
    bn_coef<<<1, 512>>>(256, g1, be1, ST, CF);

    // ---- Layer 2: 256 -> 128 (BN1 folded into W2a) ----
    launch_transpose(W2a, BT, 256, 128, CF);
    vecmat_bias<<<1, 128>>>(W2a, CF, b2a, BY, BA, 256, 128);
    launch_gemm<128, 2, 4, 0, 1>(H1, BT, Y, M, 128, 256, BY, 0, A, BA);
    launch_scatter(Y, A, eidx, NE, 32);
    launch_transpose(W2b, BT, 128, 128, nullptr);
    launch_gemm<128, 2, 4, 1, 1>(A, BT, H2, M, 128, 128, b2b, 1, nullptr, nullptr);
    col_stats<<<(M + 255) / 256, 128>>>(H2, M, 128);
    bn_coef<<<1, 512>>>(128, g2, be2, ST, CF);

    // ---- Layer 3: 128 -> 64 (BN2 folded into W3a) ----
    launch_transpose(W3a, BT, 128, 64, CF);
    vecmat_bias<<<1, 64>>>(W3a, CF, b3a, BY, BA, 128, 64);
    launch_gemm<64, 4, 2, 0, 1>(H2, BT, Y, M, 64, 128, BY, 0, A, BA);
    launch_scatter(Y, A, eidx, NE, 16);
    launch_transpose(W3b, BT, 64, 64, nullptr);
    launch_gemm<64, 4, 2, 1, 1>(A, BT, H3, M, 64, 64, b3b, 1, nullptr, nullptr);
    col_stats<<<(M + 255) / 256, 64>>>(H3, M, 64);
    bn_coef<<<1, 512>>>(64, g3, be3, ST, CF);

    // ---- Pool (BN3 inline) + head ----
    zero_f<<<(NG * 64 + 255) / 256, 256>>>(P, NG * 64);
    {
        long long tot = (long long)M * 16;
        pool_bn_add<<<(int)((tot + 255) / 256), 256>>>(H3, P, batc, CF, M);
    }
    head_kernel<<<(NG + 127) / 128, 128>>>(P, Wf1, bf1, Wf2, bf2, (float*)d_out, NG);
}

// round 16
// speedup vs baseline: 1.4265x; 1.0215x over previous
#include <cuda_runtime.h>
#include <cuda_bf16.h>
#include <cstdint>

#define NN 100000
#define NE 400000
#define NG 4096
#define BN_EPS 1e-5f

// ---------------- scratch (device globals; no allocations allowed) ----------------
__device__ float g_Y[NN * 256];        // projection output
__device__ float g_A[NN * 256];        // self + bias + aggregated neighbors
__device__ float g_H1[NN * 256];
__device__ float g_H2[NN * 128];
__device__ float g_H3[NN * 64];
__device__ float g_pool[NG * 64];
__device__ float g_stats[512];         // [0:256) col sums, [256:512) col sumsq (zero at rest)
__device__ float g_coef[512];          // [0:256) scale s, [256:512) shift t
__device__ float g_biasY[256];         // t @ W  (per-N bias for Y output)
__device__ float g_biasA[256];         // t @ W + b (per-N bias for A output)
__device__ uint32_t g_BtHi[256 * 192]; // transposed weight, packed bf16x2 hi pairs [N, K/2]
__device__ uint32_t g_BtLo[256 * 192]; // transposed weight, packed bf16x2 lo pairs [N, K/2]
__device__ int   g_is64;

// ---------------- dtype detection (int64 vs int32 indices) ----------------
__global__ void detect_dtype(const unsigned int* __restrict__ w, int n) {
    __shared__ int anyNZ;
    if (threadIdx.x == 0) anyNZ = 0;
    __syncthreads();
    for (int i = threadIdx.x; i < n; i += blockDim.x)
        if (w[2 * i + 1] != 0u) anyNZ = 1;
    __syncthreads();
    if (threadIdx.x == 0) g_is64 = (anyNZ == 0) ? 1 : 0;
}

__device__ __forceinline__ int load_idx(const void* p, long long i, int is64) {
    return is64 ? (int)((const long long*)p)[i] : ((const int*)p)[i];
}

// Split two fp32 values into packed bf16x2 hi + bf16x2 lo (low16 = v0).
__device__ __forceinline__ void split_bf16x2(float v0, float v1, uint32_t& hi, uint32_t& lo) {
    asm("cvt.rn.bf16x2.f32 %0, %1, %2;" : "=r"(hi) : "f"(v1), "f"(v0));
    float h0 = __uint_as_float(hi << 16);
    float h1 = __uint_as_float(hi & 0xFFFF0000u);
    float r0 = v0 - h0;
    float r1 = v1 - h1;
    asm("cvt.rn.bf16x2.f32 %0, %1, %2;" : "=r"(lo) : "f"(r1), "f"(r0));
}

__device__ __forceinline__ void cp4(uint32_t dst, const void* src, bool valid) {
    int sz = valid ? 4 : 0;
    asm volatile("cp.async.ca.shared.global [%0], [%1], 4, %2;"
                 :: "r"(dst), "l"(src), "r"(sz) : "memory");
}

__device__ __forceinline__ void cp16(uint32_t dst, const void* src, bool valid) {
    int sz = valid ? 16 : 0;
    asm volatile("cp.async.ca.shared.global [%0], [%1], 16, %2;"
                 :: "r"(dst), "l"(src), "r"(sz) : "memory");
}

// ---------------- weight transpose+bf16-split: [K,N] -> packed pairs [N, K2] ----------------
__global__ void transpose_w_split(const float* __restrict__ in,
                                  uint32_t* __restrict__ outHi, uint32_t* __restrict__ outLo,
                                  int K, int N, const float* __restrict__ scale) {
    __shared__ float t[32][33];
    int kx = blockIdx.y * 32, nx = blockIdx.x * 32;
    int x = threadIdx.x, y = threadIdx.y;      // 32 x 8
#pragma unroll
    for (int j = 0; j < 32; j += 8) {
        int k = kx + y + j, n = nx + x;
        float v = 0.f;
        if (k < K && n < N) {
            v = in[(long long)k * N + n];
            if (scale) v *= scale[k];
        }
        t[y + j][x] = v;
    }
    __syncthreads();
    const int K2 = (K + 1) >> 1;
    if (x < 16) {
#pragma unroll
        for (int j = 0; j < 32; j += 8) {
            int n = nx + y + j;
            int k0 = kx + 2 * x;
            if (n < N && k0 < K) {
                float v0 = t[2 * x][y + j];
                float v1 = (k0 + 1 < K) ? t[2 * x + 1][y + j] : 0.f;
                uint32_t hi, lo;
                split_bf16x2(v0, v1, hi, lo);
                long long idx = (long long)n * K2 + (kx >> 1) + x;
                outHi[idx] = hi;
                outLo[idx] = lo;
            }
        }
    }
}

// ---------------- bias correction: BY[n] = t @ W[:,n]; BA[n] = BY[n] + b[n] ----------------
__global__ void vecmat_bias(const float* __restrict__ W, const float* __restrict__ coef,
                            const float* __restrict__ b,
                            float* __restrict__ BY, float* __restrict__ BA,
                            int K, int N) {
    int n = blockIdx.x * blockDim.x + threadIdx.x;
    if (n >= N) return;
    float s = 0.f;
    for (int k = 0; k < K; k++)
        s = fmaf(coef[256 + k], W[(long long)k * N + n], s);
    BY[n] = s;
    BA[n] = s + b[n];
}

// ---------------- BN coefficients from stats (race-free; re-zero for replay) ----------------
__global__ void bn_coef(int C, const float* __restrict__ g, const float* __restrict__ be,
                        float* __restrict__ stats, float* __restrict__ coef) {
    int c = threadIdx.x;   // 512 threads
    float sum = 0.f, sq = 0.f;
    if (c < C) {
        sum = stats[c];
        sq  = stats[256 + c];           // read BEFORE anyone zeroes
    }
    __syncthreads();                    // all reads complete before zeroing
    stats[c] = 0.f;
    if (c < C) {
        float invN = 1.f / (float)NN;
        float mu = sum * invN;
        float var = fmaf(-mu, mu, sq * invN);
        float s = rsqrtf(var + BN_EPS) * g[c];
        coef[c] = s;
        coef[256 + c] = fmaf(-mu, s, be[c]);
    }
}

// ---------------- 3xBF16 mma.sync GEMM (m16n8k16), B pre-split, 2 CTAs/SM ----------------
// C[M,N] = f(A[M,K]) @ B[N,K]^T;  B given as packed bf16x2 hi/lo pair arrays [N, K2].
// f = relu if RELUIN (at fragment load). epilogue: C = (acc+bias)[relu]; opt C2 = acc+bias2.
// VEC4: 16-byte cp.async staging (requires K % 32 == 0).
// SMEM: As[2][BM*36] fp32 | Bh[2][BN_*20] u32 | Bl[2][BN_*20] u32
template <int BN_, int WM_, int WN_, int RELUIN, int VEC4>
__global__ __launch_bounds__(256, 2)
void mma_gemm(const float* __restrict__ A,
              const uint32_t* __restrict__ BtHi, const uint32_t* __restrict__ BtLo,
              float* __restrict__ C, int M, int N, int K,
              const float* __restrict__ bias, int reluOut,
              float* __restrict__ C2, const float* __restrict__ bias2) {
    constexpr int BM = 128, BK = 32, STR = 36, STRB = 20;
    constexpr int MW = BM / WM_;
    constexpr int NW = BN_ / WN_;
    constexpr int MAT = MW / 16;
    constexpr int NAT = NW / 8;
    constexpr int BH_OFF = 2 * BM * STR;
    constexpr int BL_OFF = BH_OFF + 2 * BN_ * STRB;
    extern __shared__ float smem[];
    uint32_t smem_u32;
    asm("{ .reg .u64 t; cvta.to.shared.u64 t, %1; cvt.u32.u64 %0, t; }"
        : "=r"(smem_u32) : "l"(smem));

    const int tid = threadIdx.x;
    const int wid = tid >> 5, lane = tid & 31;
    const int gid = lane >> 2, tig = lane & 3;
    const int wm = wid / WN_, wn = wid % WN_;
    const int m0 = blockIdx.y * BM;
    const int n0 = blockIdx.x * BN_;
    const int K2 = (K + 1) >> 1;

    float acc[MAT][NAT][4];
#pragma unroll
    for (int i = 0; i < MAT; i++)
#pragma unroll
        for (int j = 0; j < NAT; j++)
#pragma unroll
            for (int q = 0; q < 4; q++) acc[i][j][q] = 0.f;

    const int KT = (K + BK - 1) / BK;

    auto stage = [&](int kt, int b) {
        const int k0 = kt * BK;
        const int k0p = kt * 16;            // pair base
        if (VEC4) {
#pragma unroll
            for (int it = 0; it < (BM * 8) / 256; ++it) {
                int i = tid + it * 256;
                int row = i >> 3, c4 = (i & 7) * 4;
                int gm = m0 + row;
                bool ok = (gm < M);
                long long gi = ok ? ((long long)gm * K + k0 + c4) : 0;
                uint32_t d = smem_u32 + (uint32_t)((b * BM * STR + row * STR + c4) * 4);
                cp16(d, A + gi, ok);
            }
#pragma unroll
            for (int it = 0; it < (BN_ * 4) / 256; ++it) {
                int i = tid + it * 256;
                int n = i >> 2, c4 = (i & 3) * 4;
                int gn = n0 + n;
                bool ok = (gn < N);
                long long gi = ok ? ((long long)gn * K2 + k0p + c4) : 0;
                uint32_t dh = smem_u32 + (uint32_t)((BH_OFF + b * BN_ * STRB + n * STRB + c4) * 4);
                uint32_t dl = smem_u32 + (uint32_t)((BL_OFF + b * BN_ * STRB + n * STRB + c4) * 4);
                cp16(dh, BtHi + gi, ok);
                cp16(dl, BtLo + gi, ok);
            }
        } else {
#pragma unroll
            for (int it = 0; it < (BM * BK) / 256; ++it) {
                int i = tid + it * 256;
                int row = i >> 5, col = i & 31;
                int gm = m0 + row, gk = k0 + col;
                bool ok = (gm < M) && (gk < K);
                long long gi = ok ? ((long long)gm * K + gk) : 0;
                uint32_t d = smem_u32 + (uint32_t)((b * BM * STR + row * STR + col) * 4);
                cp4(d, A + gi, ok);
            }
#pragma unroll
            for (int it = 0; it < (BN_ * 16) / 256; ++it) {
                int i = tid + it * 256;
                int n = i >> 4, c = i & 15;
                int gn = n0 + n, j = k0p + c;
                bool ok = (gn < N) && (j < K2);
                long long gi = ok ? ((long long)gn * K2 + j) : 0;
                uint32_t dh = smem_u32 + (uint32_t)((BH_OFF + b * BN_ * STRB + n * STRB + c) * 4);
                uint32_t dl = smem_u32 + (uint32_t)((BL_OFF + b * BN_ * STRB + n * STRB + c) * 4);
                cp4(dh, BtHi + gi, ok);
                cp4(dl, BtLo + gi, ok);
            }
        }
        asm volatile("cp.async.commit_group;" ::: "memory");
    };

    stage(0, 0);
    for (int kt = 0; kt < KT; ++kt) {
        if (kt + 1 < KT) {
            stage(kt + 1, (kt + 1) & 1);
            asm volatile("cp.async.wait_group 1;" ::: "memory");
        } else {
            asm volatile("cp.async.wait_group 0;" ::: "memory");
        }
        __syncthreads();

        const float* As = smem + (kt & 1) * BM * STR;
        const uint32_t* Bsh = (const uint32_t*)smem + BH_OFF + (kt & 1) * BN_ * STRB;
        const uint32_t* Bsl = (const uint32_t*)smem + BL_OFF + (kt & 1) * BN_ * STRB;

#pragma unroll
        for (int ks = 0; ks < 2; ks++) {          // two K=16 mma steps per 32-K tile
            const int kb = ks * 16 + tig * 2;     // fp32 k base for A
            const int jb = ks * 8 + tig;          // pair index for B
            uint32_t ah[MAT][4], al[MAT][4];
#pragma unroll
            for (int im = 0; im < MAT; im++) {
                int ar = wm * MW + im * 16 + gid;
                float2 v00 = *(const float2*)&As[ar * STR + kb];
                float2 v10 = *(const float2*)&As[(ar + 8) * STR + kb];
                float2 v01 = *(const float2*)&As[ar * STR + kb + 8];
                float2 v11 = *(const float2*)&As[(ar + 8) * STR + kb + 8];
                if (RELUIN) {
                    v00.x = fmaxf(v00.x, 0.f); v00.y = fmaxf(v00.y, 0.f);
                    v10.x = fmaxf(v10.x, 0.f); v10.y = fmaxf(v10.y, 0.f);
                    v01.x = fmaxf(v01.x, 0.f); v01.y = fmaxf(v01.y, 0.f);
                    v11.x = fmaxf(v11.x, 0.f); v11.y = fmaxf(v11.y, 0.f);
                }
                split_bf16x2(v00.x, v00.y, ah[im][0], al[im][0]);
                split_bf16x2(v10.x, v10.y, ah[im][1], al[im][1]);
                split_bf16x2(v01.x, v01.y, ah[im][2], al[im][2]);
                split_bf16x2(v11.x, v11.y, ah[im][3], al[im][3]);
            }
#pragma unroll
            for (int in = 0; in < NAT; in++) {
                int br = wn * NW + in * 8 + gid;
                uint32_t bh0 = Bsh[br * STRB + jb];
                uint32_t bh1 = Bsh[br * STRB + jb + 4];
                uint32_t bl0 = Bsl[br * STRB + jb];
                uint32_t bl1 = Bsl[br * STRB + jb + 4];
#pragma unroll
                for (int im = 0; im < MAT; im++) {
                    asm volatile(
                        "mma.sync.aligned.m16n8k16.row.col.f32.bf16.bf16.f32 "
                        "{%0,%1,%2,%3}, {%4,%5,%6,%7}, {%8,%9}, {%0,%1,%2,%3};"
                        : "+f"(acc[im][in][0]), "+f"(acc[im][in][1]),
                          "+f"(acc[im][in][2]), "+f"(acc[im][in][3])
                        : "r"(al[im][0]), "r"(al[im][1]), "r"(al[im][2]), "r"(al[im][3]),
                          "r"(bh0), "r"(bh1));
                    asm volatile(
                        "mma.sync.aligned.m16n8k16.row.col.f32.bf16.bf16.f32 "
                        "{%0,%1,%2,%3}, {%4,%5,%6,%7}, {%8,%9}, {%0,%1,%2,%3};"
                        : "+f"(acc[im][in][0]), "+f"(acc[im][in][1]),
                          "+f"(acc[im][in][2]), "+f"(acc[im][in][3])
                        : "r"(ah[im][0]), "r"(ah[im][1]), "r"(ah[im][2]), "r"(ah[im][3]),
                          "r"(bl0), "r"(bl1));
                    asm volatile(
                        "mma.sync.aligned.m16n8k16.row.col.f32.bf16.bf16.f32 "
                        "{%0,%1,%2,%3}, {%4,%5,%6,%7}, {%8,%9}, {%0,%1,%2,%3};"
                        : "+f"(acc[im][in][0]), "+f"(acc[im][in][1]),
                          "+f"(acc[im][in][2]), "+f"(acc[im][in][3])
                        : "r"(ah[im][0]), "r"(ah[im][1]), "r"(ah[im][2]), "r"(ah[im][3]),
                          "r"(bh0), "r"(bh1));
                }
            }
        }
        __syncthreads();
    }

    // ---- epilogue ----
#pragma unroll
    for (int im = 0; im < MAT; im++) {
        int r0 = m0 + wm * MW + im * 16 + gid;
        int r1 = r0 + 8;
#pragma unroll
        for (int in = 0; in < NAT; in++) {
            int cc = n0 + wn * NW + in * 8 + tig * 2;
            float v0 = acc[im][in][0], v1 = acc[im][in][1];
            float v2 = acc[im][in][2], v3 = acc[im][in][3];
            if (C2) {
                float2 b2 = *(const float2*)&bias2[cc];
                if (r0 < M) *(float2*)&C2[(long long)r0 * N + cc] = make_float2(v0 + b2.x, v1 + b2.y);
                if (r1 < M) *(float2*)&C2[(long long)r1 * N + cc] = make_float2(v2 + b2.x, v3 + b2.y);
            }
            if (bias) {
                float2 bv = *(const float2*)&bias[cc];
                v0 += bv.x; v1 += bv.y; v2 += bv.x; v3 += bv.y;
            }
            if (reluOut) {
                v0 = fmaxf(v0, 0.f); v1 = fmaxf(v1, 0.f);
                v2 = fmaxf(v2, 0.f); v3 = fmaxf(v3, 0.f);
            }
            if (r0 < M) *(float2*)&C[(long long)r0 * N + cc] = make_float2(v0, v1);
            if (r1 < M) *(float2*)&C[(long long)r1 * N + cc] = make_float2(v2, v3);
        }
    }
}

// ---------------- edge scatter: A[dst] += Y[src], MLP=4 per thread ----------------
__global__ void scatter_add(const float* __restrict__ Y, float* __restrict__ A,
                            const void* __restrict__ eidx, int E, int C4) {
    const int is64 = g_is64;
    long long total = (long long)E * C4;    // divisible by 4 for all layers
    long long q = total >> 2;
    long long i0 = (long long)blockIdx.x * blockDim.x + threadIdx.x;
    if (i0 >= q) return;
    const int C = C4 * 4;

    float4 v[4];
    float* p[4];
#pragma unroll
    for (int u = 0; u < 4; u++) {
        long long i = i0 + u * q;
        int e = (int)(i / C4), c = (int)(i % C4) * 4;
        int src = load_idx(eidx, e, is64);
        int dst = load_idx(eidx, (long long)E + e, is64);
        v[u] = *(const float4*)&Y[(long long)src * C + c];
        p[u] = &A[(long long)dst * C + c];
    }
#pragma unroll
    for (int u = 0; u < 4; u++) {
        asm volatile("red.global.add.v4.f32 [%0], {%1, %2, %3, %4};"
                     :: "l"(p[u]), "f"(v[u].x), "f"(v[u].y), "f"(v[u].z), "f"(v[u].w) : "memory");
    }
}

// ---------------- batchnorm statistics (standalone, proven) ----------------
__global__ void zero_f(float* __restrict__ p, int n) {
    int i = blockIdx.x * blockDim.x + threadIdx.x;
    if (i < n) p[i] = 0.f;
}

__global__ void col_stats(const float* __restrict__ H, int M, int C) {
    const int c = threadIdx.x;            // blockDim.x == C
    const int r0 = blockIdx.x * 256;
    const int r1 = min(r0 + 256, M);
    float s = 0.f, q = 0.f;
    for (int r = r0; r < r1; ++r) {
        float v = H[(long long)r * C + c];
        s += v;
        q = fmaf(v, v, q);
    }
    atomicAdd(&g_stats[c], s);
    atomicAdd(&g_stats[256 + c], q);
}

// ---------------- pooling (applies BN3 inline) + head ----------------
__global__ void pool_bn_add(const float* __restrict__ H, float* __restrict__ P,
                            const void* __restrict__ batch,
                            const float* __restrict__ coef, int M) {
    const int is64 = g_is64;
    long long i = (long long)blockIdx.x * blockDim.x + threadIdx.x;
    long long total = (long long)M * 16;      // C=64 -> 16 float4 per node
    if (i >= total) return;
    int node = (int)(i / 16);
    int c = (int)(i % 16) * 4;
    int gph = load_idx(batch, node, is64);
    float4 v = *(const float4*)&H[(long long)node * 64 + c];
    float4 s = *(const float4*)&coef[c];
    float4 t = *(const float4*)&coef[256 + c];
    v.x = fmaf(v.x, s.x, t.x); v.y = fmaf(v.y, s.y, t.y);
    v.z = fmaf(v.z, s.z, t.z); v.w = fmaf(v.w, s.w, t.w);
    float* p = &P[(long long)gph * 64 + c];
    asm volatile("red.global.add.v4.f32 [%0], {%1, %2, %3, %4};"
                 :: "l"(p), "f"(v.x), "f"(v.y), "f"(v.z), "f"(v.w) : "memory");
}

__global__ void head_kernel(const float* __restrict__ P,
                            const float* __restrict__ Wf1, const float* __restrict__ bf1,
                            const float* __restrict__ Wf2, const float* __restrict__ bf2,
                            float* __restrict__ out, int G) {
    int g = blockIdx.x * blockDim.x + threadIdx.x;
    if (g >= G) return;
    float acc[16];
#pragma unroll
    for (int j = 0; j < 16; j++) acc[j] = bf1[j];
    const float* p = &P[(long long)g * 64];
    for (int k = 0; k < 64; k++) {
        float pv = p[k];
#pragma unroll
        for (int j = 0; j < 16; j++) acc[j] = fmaf(pv, Wf1[k * 16 + j], acc[j]);
    }
    float o = bf2[0];
#pragma unroll
    for (int j = 0; j < 16; j++) o = fmaf(fmaxf(acc[j], 0.f), Wf2[j], o);
    out[g] = fmaxf(o, 0.f);
}

// ---------------- host launcher ----------------
static void launch_transpose(const float* W, uint32_t* BtHi, uint32_t* BtLo,
                             int K, int N, const float* scale) {
    dim3 grid((N + 31) / 32, (K + 31) / 32);
    transpose_w_split<<<grid, dim3(32, 8)>>>(W, BtHi, BtLo, K, N, scale);
}

static void launch_scatter(const float* Y, float* A, const void* eidx, int E, int C4) {
    long long total = (long long)E * C4;
    long long q = total >> 2;
    scatter_add<<<(int)((q + 255) / 256), 256>>>(Y, A, eidx, E, C4);
}

template <int BN_, int WM_, int WN_, int RELUIN, int VEC4>
static void launch_gemm(const float* A, const uint32_t* BtHi, const uint32_t* BtLo,
                        float* C, int M, int N, int K, const float* bias,
                        int reluOut, float* C2, const float* bias2) {
    constexpr int SMEM_BYTES = (2 * 128 * 36 + 4 * BN_ * 20) * 4;
    static bool attr_set = false;
    if (!attr_set) {
        cudaFuncSetAttribute(mma_gemm<BN_, WM_, WN_, RELUIN, VEC4>,
                             cudaFuncAttributeMaxDynamicSharedMemorySize, SMEM_BYTES);
        attr_set = true;
    }
    dim3 grid(N / BN_, (M + 127) / 128);
    mma_gemm<BN_, WM_, WN_, RELUIN, VEC4><<<grid, 256, SMEM_BYTES>>>(
        A, BtHi, BtLo, C, M, N, K, bias, reluOut, C2, bias2);
}

extern "C" void kernel_launch(void* const* d_in, const int* in_sizes, int n_in,
                              void* d_out, int out_size) {
    const float* x    = (const float*)d_in[0];
    const void*  eidx = d_in[1];
    const void*  batc = d_in[2];
    const float* W1a = (const float*)d_in[3];  const float* b1a = (const float*)d_in[4];
    const float* W1b = (const float*)d_in[5];  const float* b1b = (const float*)d_in[6];
    const float* g1  = (const float*)d_in[7];  const float* be1 = (const float*)d_in[8];
    const float* W2a = (const float*)d_in[9];  const float* b2a = (const float*)d_in[10];
    const float* W2b = (const float*)d_in[11]; const float* b2b = (const float*)d_in[12];
    const float* g2  = (const float*)d_in[13]; const float* be2 = (const float*)d_in[14];
    const float* W3a = (const float*)d_in[15]; const float* b3a = (const float*)d_in[16];
    const float* W3b = (const float*)d_in[17]; const float* b3b = (const float*)d_in[18];
    const float* g3  = (const float*)d_in[19]; const float* be3 = (const float*)d_in[20];
    const float* Wf1 = (const float*)d_in[21]; const float* bf1 = (const float*)d_in[22];
    const float* Wf2 = (const float*)d_in[23]; const float* bf2 = (const float*)d_in[24];

    float *Y, *A, *H1, *H2, *H3, *P, *ST, *CF, *BY, *BA;
    uint32_t *BH, *BL;
    cudaGetSymbolAddress((void**)&Y,  g_Y);
    cudaGetSymbolAddress((void**)&A,  g_A);
    cudaGetSymbolAddress((void**)&H1, g_H1);
    cudaGetSymbolAddress((void**)&H2, g_H2);
    cudaGetSymbolAddress((void**)&H3, g_H3);
    cudaGetSymbolAddress((void**)&P,  g_pool);
    cudaGetSymbolAddress((void**)&ST, g_stats);
    cudaGetSymbolAddress((void**)&CF, g_coef);
    cudaGetSymbolAddress((void**)&BY, g_biasY);
    cudaGetSymbolAddress((void**)&BA, g_biasA);
    cudaGetSymbolAddress((void**)&BH, g_BtHi);
    cudaGetSymbolAddress((void**)&BL, g_BtLo);

    detect_dtype<<<1, 256>>>((const unsigned int*)eidx, 1024);

    const int M = NN;

    // ---- Layer 1: 373 -> 256 (no BN on input; K=373 -> scalar A staging) ----
    launch_transpose(W1a, BH, BL, 373, 256, nullptr);
    launch_gemm<128, 2, 4, 0, 0>(x, BH, BL, Y, M, 256, 373, nullptr, 0, A, b1a);
    launch_scatter(Y, A, eidx, NE, 64);
    launch_transpose(W1b, BH, BL, 256, 256, nullptr);
    launch_gemm<128, 2, 4, 1, 1>(A, BH, BL, H1, M, 256, 256, b1b, 1, nullptr, nullptr);
    col_stats<<<(M + 255) / 256, 256>>>(H1, M, 256);
    bn_coef<<<1, 512>>>(256, g1, be1, ST, CF);

    // ---- Layer 2: 256 -> 128 (BN1 folded into W2a) ----
    launch_transpose(W2a, BH, BL, 256, 128, CF);
    vecmat_bias<<<1, 128>>>(W2a, CF, b2a, BY, BA, 256, 128);
    launch_gemm<128, 2, 4, 0, 1>(H1, BH, BL, Y, M, 128, 256, BY, 0, A, BA);
    launch_scatter(Y, A, eidx, NE, 32);
    launch_transpose(W2b, BH, BL, 128, 128, nullptr);
    launch_gemm<128, 2, 4, 1, 1>(A, BH, BL, H2, M, 128, 128, b2b, 1, nullptr, nullptr);
    col_stats<<<(M + 255) / 256, 128>>>(H2, M, 128);
    bn_coef<<<1, 512>>>(128, g2, be2, ST, CF);

    // ---- Layer 3: 128 -> 64 (BN2 folded into W3a) ----
    launch_transpose(W3a, BH, BL, 128, 64, CF);
    vecmat_bias<<<1, 64>>>(W3a, CF, b3a, BY, BA, 128, 64);
    launch_gemm<64, 4, 2, 0, 1>(H2, BH, BL, Y, M, 64, 128, BY, 0, A, BA);
    launch_scatter(Y, A, eidx, NE, 16);
    launch_transpose(W3b, BH, BL, 64, 64, nullptr);
    launch_gemm<64, 4, 2, 1, 1>(A, BH, BL, H3, M, 64, 64, b3b, 1, nullptr, nullptr);
    col_stats<<<(M + 255) / 256, 64>>>(H3, M, 64);
    bn_coef<<<1, 512>>>(64, g3, be3, ST, CF);

    // ---- Pool (BN3 inline) + head ----
    zero_f<<<(NG * 64 + 255) / 256, 256>>>(P, NG * 64);
    {
        long long tot = (long long)M * 16;
        pool_bn_add<<<(int)((tot + 255) / 256), 256>>>(H3, P, batc, CF, M);
    }
    head_kernel<<<(NG + 127) / 128, 128>>>(P, Wf1, bf1, Wf2, bf2, (float*)d_out, NG);
}

// round 17
// speedup vs baseline: 1.4763x; 1.0349x over previous
#include <cuda_runtime.h>
#include <cuda_bf16.h>
#include <cstdint>

#define NN 100000
#define NE 400000
#define NG 4096
#define BN_EPS 1e-5f

// ---------------- scratch (device globals; no allocations allowed) ----------------
__device__ float g_Y[NN * 256];        // projection output
__device__ float g_A[NN * 256];        // self + bias + aggregated neighbors
__device__ float g_H1[NN * 256];
__device__ float g_H2[NN * 128];
__device__ float g_H3[NN * 64];
__device__ float g_pool[NG * 64];
__device__ float g_stats[512];         // [0:256) col sums, [256:512) col sumsq (zero at rest)
__device__ float g_coef[512];          // [0:256) scale s, [256:512) shift t
__device__ float g_biasY[256];         // t @ W  (per-N bias for Y output)
__device__ float g_biasA[256];         // t @ W + b (per-N bias for A output)
__device__ uint32_t g_BtHi[256 * 192]; // transposed weight, packed bf16x2 hi pairs [N, K/2]
__device__ uint32_t g_BtLo[256 * 192]; // transposed weight, packed bf16x2 lo pairs [N, K/2]
__device__ int   g_is64;

// ---------------- dtype detection (int64 vs int32 indices) ----------------
__global__ void detect_dtype(const unsigned int* __restrict__ w, int n) {
    __shared__ int anyNZ;
    if (threadIdx.x == 0) anyNZ = 0;
    __syncthreads();
    for (int i = threadIdx.x; i < n; i += blockDim.x)
        if (w[2 * i + 1] != 0u) anyNZ = 1;
    __syncthreads();
    if (threadIdx.x == 0) g_is64 = (anyNZ == 0) ? 1 : 0;
}

__device__ __forceinline__ int load_idx(const void* p, long long i, int is64) {
    return is64 ? (int)((const long long*)p)[i] : ((const int*)p)[i];
}

// Split two fp32 values into packed bf16x2 hi + bf16x2 lo (low16 = v0).
__device__ __forceinline__ void split_bf16x2(float v0, float v1, uint32_t& hi, uint32_t& lo) {
    asm("cvt.rn.bf16x2.f32 %0, %1, %2;" : "=r"(hi) : "f"(v1), "f"(v0));
    float h0 = __uint_as_float(hi << 16);
    float h1 = __uint_as_float(hi & 0xFFFF0000u);
    float r0 = v0 - h0;
    float r1 = v1 - h1;
    asm("cvt.rn.bf16x2.f32 %0, %1, %2;" : "=r"(lo) : "f"(r1), "f"(r0));
}

__device__ __forceinline__ void cp4(uint32_t dst, const void* src, bool valid) {
    int sz = valid ? 4 : 0;
    asm volatile("cp.async.ca.shared.global [%0], [%1], 4, %2;"
                 :: "r"(dst), "l"(src), "r"(sz) : "memory");
}

__device__ __forceinline__ void cp16(uint32_t dst, const void* src, bool valid) {
    int sz = valid ? 16 : 0;
    asm volatile("cp.async.ca.shared.global [%0], [%1], 16, %2;"
                 :: "r"(dst), "l"(src), "r"(sz) : "memory");
}

// ---------------- weight transpose+bf16-split: [K,N] -> packed pairs [N, K2] ----------------
__global__ void transpose_w_split(const float* __restrict__ in,
                                  uint32_t* __restrict__ outHi, uint32_t* __restrict__ outLo,
                                  int K, int N, const float* __restrict__ scale) {
    __shared__ float t[32][33];
    int kx = blockIdx.y * 32, nx = blockIdx.x * 32;
    int x = threadIdx.x, y = threadIdx.y;      // 32 x 8
#pragma unroll
    for (int j = 0; j < 32; j += 8) {
        int k = kx + y + j, n = nx + x;
        float v = 0.f;
        if (k < K && n < N) {
            v = in[(long long)k * N + n];
            if (scale) v *= scale[k];
        }
        t[y + j][x] = v;
    }
    __syncthreads();
    const int K2 = (K + 1) >> 1;
    if (x < 16) {
#pragma unroll
        for (int j = 0; j < 32; j += 8) {
            int n = nx + y + j;
            int k0 = kx + 2 * x;
            if (n < N && k0 < K) {
                float v0 = t[2 * x][y + j];
                float v1 = (k0 + 1 < K) ? t[2 * x + 1][y + j] : 0.f;
                uint32_t hi, lo;
                split_bf16x2(v0, v1, hi, lo);
                long long idx = (long long)n * K2 + (kx >> 1) + x;
                outHi[idx] = hi;
                outLo[idx] = lo;
            }
        }
    }
}

// ---------------- bias correction: BY[n] = t @ W[:,n]; BA[n] = BY[n] + b[n] ----------------
__global__ void vecmat_bias(const float* __restrict__ W, const float* __restrict__ coef,
                            const float* __restrict__ b,
                            float* __restrict__ BY, float* __restrict__ BA,
                            int K, int N) {
    int n = blockIdx.x * blockDim.x + threadIdx.x;
    if (n >= N) return;
    float s = 0.f;
    for (int k = 0; k < K; k++)
        s = fmaf(coef[256 + k], W[(long long)k * N + n], s);
    BY[n] = s;
    BA[n] = s + b[n];
}

// ---------------- BN coefficients from stats (race-free; re-zero for replay) ----------------
__global__ void bn_coef(int C, const float* __restrict__ g, const float* __restrict__ be,
                        float* __restrict__ stats, float* __restrict__ coef) {
    int c = threadIdx.x;   // 512 threads
    float sum = 0.f, sq = 0.f;
    if (c < C) {
        sum = stats[c];
        sq  = stats[256 + c];           // read BEFORE anyone zeroes
    }
    __syncthreads();                    // all reads complete before zeroing
    stats[c] = 0.f;
    if (c < C) {
        float invN = 1.f / (float)NN;
        float mu = sum * invN;
        float var = fmaf(-mu, mu, sq * invN);
        float s = rsqrtf(var + BN_EPS) * g[c];
        coef[c] = s;
        coef[256 + c] = fmaf(-mu, s, be[c]);
    }
}

// ---------------- 3xBF16 mma.sync GEMM (m16n8k16), B pre-split, 2 CTAs/SM ----------------
// C[M,N] = f(A[M,K]) @ B[N,K]^T;  B given as packed bf16x2 hi/lo pair arrays [N, K2].
// f = relu if RELUIN (at fragment load). epilogue: C = (acc+bias)[relu]; opt C2 = acc+bias2;
// optional stats: per-column sum/sumsq of stored C (atomicAdd into stats[0:256)/[256:512)).
// VEC4: 16-byte cp.async staging (requires K % 32 == 0).
// SMEM: As[2][BM*36] fp32 | Bh[2][BN_*20] u32 | Bl[2][BN_*20] u32
template <int BN_, int WM_, int WN_, int RELUIN, int VEC4, int STATS>
__global__ __launch_bounds__(256, 2)
void mma_gemm(const float* __restrict__ A,
              const uint32_t* __restrict__ BtHi, const uint32_t* __restrict__ BtLo,
              float* __restrict__ C, int M, int N, int K,
              const float* __restrict__ bias, int reluOut,
              float* __restrict__ C2, const float* __restrict__ bias2,
              float* __restrict__ stats) {
    constexpr int BM = 128, BK = 32, STR = 36, STRB = 20;
    constexpr int MW = BM / WM_;
    constexpr int NW = BN_ / WN_;
    constexpr int MAT = MW / 16;
    constexpr int NAT = NW / 8;
    constexpr int BH_OFF = 2 * BM * STR;
    constexpr int BL_OFF = BH_OFF + 2 * BN_ * STRB;
    extern __shared__ float smem[];
    uint32_t smem_u32;
    asm("{ .reg .u64 t; cvta.to.shared.u64 t, %1; cvt.u32.u64 %0, t; }"
        : "=r"(smem_u32) : "l"(smem));

    const int tid = threadIdx.x;
    const int wid = tid >> 5, lane = tid & 31;
    const int gid = lane >> 2, tig = lane & 3;
    const int wm = wid / WN_, wn = wid % WN_;
    const int m0 = blockIdx.y * BM;
    const int n0 = blockIdx.x * BN_;
    const int K2 = (K + 1) >> 1;

    float acc[MAT][NAT][4];
#pragma unroll
    for (int i = 0; i < MAT; i++)
#pragma unroll
        for (int j = 0; j < NAT; j++)
#pragma unroll
            for (int q = 0; q < 4; q++) acc[i][j][q] = 0.f;

    const int KT = (K + BK - 1) / BK;

    auto stage = [&](int kt, int b) {
        const int k0 = kt * BK;
        const int k0p = kt * 16;            // pair base
        if (VEC4) {
#pragma unroll
            for (int it = 0; it < (BM * 8) / 256; ++it) {
                int i = tid + it * 256;
                int row = i >> 3, c4 = (i & 7) * 4;
                int gm = m0 + row;
                bool ok = (gm < M);
                long long gi = ok ? ((long long)gm * K + k0 + c4) : 0;
                uint32_t d = smem_u32 + (uint32_t)((b * BM * STR + row * STR + c4) * 4);
                cp16(d, A + gi, ok);
            }
#pragma unroll
            for (int it = 0; it < (BN_ * 4) / 256; ++it) {
                int i = tid + it * 256;
                int n = i >> 2, c4 = (i & 3) * 4;
                int gn = n0 + n;
                bool ok = (gn < N);
                long long gi = ok ? ((long long)gn * K2 + k0p + c4) : 0;
                uint32_t dh = smem_u32 + (uint32_t)((BH_OFF + b * BN_ * STRB + n * STRB + c4) * 4);
                uint32_t dl = smem_u32 + (uint32_t)((BL_OFF + b * BN_ * STRB + n * STRB + c4) * 4);
                cp16(dh, BtHi + gi, ok);
                cp16(dl, BtLo + gi, ok);
            }
        } else {
#pragma unroll
            for (int it = 0; it < (BM * BK) / 256; ++it) {
                int i = tid + it * 256;
                int row = i >> 5, col = i & 31;
                int gm = m0 + row, gk = k0 + col;
                bool ok = (gm < M) && (gk < K);
                long long gi = ok ? ((long long)gm * K + gk) : 0;
                uint32_t d = smem_u32 + (uint32_t)((b * BM * STR + row * STR + col) * 4);
                cp4(d, A + gi, ok);
            }
#pragma unroll
            for (int it = 0; it < (BN_ * 16) / 256; ++it) {
                int i = tid + it * 256;
                int n = i >> 4, c = i & 15;
                int gn = n0 + n, j = k0p + c;
                bool ok = (gn < N) && (j < K2);
                long long gi = ok ? ((long long)gn * K2 + j) : 0;
                uint32_t dh = smem_u32 + (uint32_t)((BH_OFF + b * BN_ * STRB + n * STRB + c) * 4);
                uint32_t dl = smem_u32 + (uint32_t)((BL_OFF + b * BN_ * STRB + n * STRB + c) * 4);
                cp4(dh, BtHi + gi, ok);
                cp4(dl, BtLo + gi, ok);
            }
        }
        asm volatile("cp.async.commit_group;" ::: "memory");
    };

    stage(0, 0);
    for (int kt = 0; kt < KT; ++kt) {
        if (kt + 1 < KT) {
            stage(kt + 1, (kt + 1) & 1);
            asm volatile("cp.async.wait_group 1;" ::: "memory");
        } else {
            asm volatile("cp.async.wait_group 0;" ::: "memory");
        }
        __syncthreads();

        const float* As = smem + (kt & 1) * BM * STR;
        const uint32_t* Bsh = (const uint32_t*)smem + BH_OFF + (kt & 1) * BN_ * STRB;
        const uint32_t* Bsl = (const uint32_t*)smem + BL_OFF + (kt & 1) * BN_ * STRB;

#pragma unroll
        for (int ks = 0; ks < 2; ks++) {          // two K=16 mma steps per 32-K tile
            const int kb = ks * 16 + tig * 2;     // fp32 k base for A
            const int jb = ks * 8 + tig;          // pair index for B
            uint32_t ah[MAT][4], al[MAT][4];
#pragma unroll
            for (int im = 0; im < MAT; im++) {
                int ar = wm * MW + im * 16 + gid;
                float2 v00 = *(const float2*)&As[ar * STR + kb];
                float2 v10 = *(const float2*)&As[(ar + 8) * STR + kb];
                float2 v01 = *(const float2*)&As[ar * STR + kb + 8];
                float2 v11 = *(const float2*)&As[(ar + 8) * STR + kb + 8];
                if (RELUIN) {
                    v00.x = fmaxf(v00.x, 0.f); v00.y = fmaxf(v00.y, 0.f);
                    v10.x = fmaxf(v10.x, 0.f); v10.y = fmaxf(v10.y, 0.f);
                    v01.x = fmaxf(v01.x, 0.f); v01.y = fmaxf(v01.y, 0.f);
                    v11.x = fmaxf(v11.x, 0.f); v11.y = fmaxf(v11.y, 0.f);
                }
                split_bf16x2(v00.x, v00.y, ah[im][0], al[im][0]);
                split_bf16x2(v10.x, v10.y, ah[im][1], al[im][1]);
                split_bf16x2(v01.x, v01.y, ah[im][2], al[im][2]);
                split_bf16x2(v11.x, v11.y, ah[im][3], al[im][3]);
            }
#pragma unroll
            for (int in = 0; in < NAT; in++) {
                int br = wn * NW + in * 8 + gid;
                uint32_t bh0 = Bsh[br * STRB + jb];
                uint32_t bh1 = Bsh[br * STRB + jb + 4];
                uint32_t bl0 = Bsl[br * STRB + jb];
                uint32_t bl1 = Bsl[br * STRB + jb + 4];
#pragma unroll
                for (int im = 0; im < MAT; im++) {
                    asm volatile(
                        "mma.sync.aligned.m16n8k16.row.col.f32.bf16.bf16.f32 "
                        "{%0,%1,%2,%3}, {%4,%5,%6,%7}, {%8,%9}, {%0,%1,%2,%3};"
                        : "+f"(acc[im][in][0]), "+f"(acc[im][in][1]),
                          "+f"(acc[im][in][2]), "+f"(acc[im][in][3])
                        : "r"(al[im][0]), "r"(al[im][1]), "r"(al[im][2]), "r"(al[im][3]),
                          "r"(bh0), "r"(bh1));
                    asm volatile(
                        "mma.sync.aligned.m16n8k16.row.col.f32.bf16.bf16.f32 "
                        "{%0,%1,%2,%3}, {%4,%5,%6,%7}, {%8,%9}, {%0,%1,%2,%3};"
                        : "+f"(acc[im][in][0]), "+f"(acc[im][in][1]),
                          "+f"(acc[im][in][2]), "+f"(acc[im][in][3])
                        : "r"(ah[im][0]), "r"(ah[im][1]), "r"(ah[im][2]), "r"(ah[im][3]),
                          "r"(bl0), "r"(bl1));
                    asm volatile(
                        "mma.sync.aligned.m16n8k16.row.col.f32.bf16.bf16.f32 "
                        "{%0,%1,%2,%3}, {%4,%5,%6,%7}, {%8,%9}, {%0,%1,%2,%3};"
                        : "+f"(acc[im][in][0]), "+f"(acc[im][in][1]),
                          "+f"(acc[im][in][2]), "+f"(acc[im][in][3])
                        : "r"(ah[im][0]), "r"(ah[im][1]), "r"(ah[im][2]), "r"(ah[im][3]),
                          "r"(bh0), "r"(bh1));
                }
            }
        }
        __syncthreads();
    }

    // ---- epilogue ----
    float cs[NAT][2], cq[NAT][2];
    if (STATS) {
#pragma unroll
        for (int in = 0; in < NAT; in++) {
            cs[in][0] = cs[in][1] = 0.f;
            cq[in][0] = cq[in][1] = 0.f;
        }
    }

#pragma unroll
    for (int im = 0; im < MAT; im++) {
        int r0 = m0 + wm * MW + im * 16 + gid;
        int r1 = r0 + 8;
#pragma unroll
        for (int in = 0; in < NAT; in++) {
            int cc = n0 + wn * NW + in * 8 + tig * 2;
            float v0 = acc[im][in][0], v1 = acc[im][in][1];
            float v2 = acc[im][in][2], v3 = acc[im][in][3];
            if (C2) {
                float2 b2 = *(const float2*)&bias2[cc];
                if (r0 < M) *(float2*)&C2[(long long)r0 * N + cc] = make_float2(v0 + b2.x, v1 + b2.y);
                if (r1 < M) *(float2*)&C2[(long long)r1 * N + cc] = make_float2(v2 + b2.x, v3 + b2.y);
            }
            if (bias) {
                float2 bv = *(const float2*)&bias[cc];
                v0 += bv.x; v1 += bv.y; v2 += bv.x; v3 += bv.y;
            }
            if (reluOut) {
                v0 = fmaxf(v0, 0.f); v1 = fmaxf(v1, 0.f);
                v2 = fmaxf(v2, 0.f); v3 = fmaxf(v3, 0.f);
            }
            if (r0 < M) *(float2*)&C[(long long)r0 * N + cc] = make_float2(v0, v1);
            if (r1 < M) *(float2*)&C[(long long)r1 * N + cc] = make_float2(v2, v3);
            if (STATS) {
                if (r0 < M) {
                    cs[in][0] += v0; cs[in][1] += v1;
                    cq[in][0] = fmaf(v0, v0, cq[in][0]);
                    cq[in][1] = fmaf(v1, v1, cq[in][1]);
                }
                if (r1 < M) {
                    cs[in][0] += v2; cs[in][1] += v3;
                    cq[in][0] = fmaf(v2, v2, cq[in][0]);
                    cq[in][1] = fmaf(v3, v3, cq[in][1]);
                }
            }
        }
    }

    if (STATS) {
#pragma unroll
        for (int in = 0; in < NAT; in++) {
#pragma unroll
            for (int h = 0; h < 2; h++) {
                float s = cs[in][h], q = cq[in][h];
#pragma unroll
                for (int d = 4; d < 32; d <<= 1) {
                    s += __shfl_xor_sync(0xFFFFFFFFu, s, d);
                    q += __shfl_xor_sync(0xFFFFFFFFu, q, d);
                }
                if (gid == 0) {
                    int cc = n0 + wn * NW + in * 8 + tig * 2 + h;
                    atomicAdd(&stats[cc], s);
                    atomicAdd(&stats[256 + cc], q);
                }
            }
        }
    }
}

// ---------------- edge scatter: A[dst] += Y[src], MLP=2 per thread (proven) ----------------
__global__ void scatter_add(const float* __restrict__ Y, float* __restrict__ A,
                            const void* __restrict__ eidx, int E, int C4) {
    const int is64 = g_is64;
    long long total = (long long)E * C4;
    long long half = (total + 1) >> 1;
    long long i0 = (long long)blockIdx.x * blockDim.x + threadIdx.x;
    if (i0 >= half) return;
    long long i1 = i0 + half;
    const int C = C4 * 4;

    int e0 = (int)(i0 / C4), c0 = (int)(i0 % C4) * 4;
    int src0 = load_idx(eidx, e0, is64);
    int dst0 = load_idx(eidx, (long long)E + e0, is64);
    float4 v0 = *(const float4*)&Y[(long long)src0 * C + c0];

    bool has1 = (i1 < total);
    int e1 = 0, c1 = 0, src1 = 0, dst1 = 0;
    float4 v1 = make_float4(0.f, 0.f, 0.f, 0.f);
    if (has1) {
        e1 = (int)(i1 / C4); c1 = (int)(i1 % C4) * 4;
        src1 = load_idx(eidx, e1, is64);
        dst1 = load_idx(eidx, (long long)E + e1, is64);
        v1 = *(const float4*)&Y[(long long)src1 * C + c1];
    }

    float* p0 = &A[(long long)dst0 * C + c0];
    asm volatile("red.global.add.v4.f32 [%0], {%1, %2, %3, %4};"
                 :: "l"(p0), "f"(v0.x), "f"(v0.y), "f"(v0.z), "f"(v0.w) : "memory");
    if (has1) {
        float* p1 = &A[(long long)dst1 * C + c1];
        asm volatile("red.global.add.v4.f32 [%0], {%1, %2, %3, %4};"
                     :: "l"(p1), "f"(v1.x), "f"(v1.y), "f"(v1.z), "f"(v1.w) : "memory");
    }
}

// ---------------- misc small kernels ----------------
__global__ void zero_f(float* __restrict__ p, int n) {
    int i = blockIdx.x * blockDim.x + threadIdx.x;
    if (i < n) p[i] = 0.f;
}

// ---------------- pooling (applies BN3 inline) + head ----------------
__global__ void pool_bn_add(const float* __restrict__ H, float* __restrict__ P,
                            const void* __restrict__ batch,
                            const float* __restrict__ coef, int M) {
    const int is64 = g_is64;
    long long i = (long long)blockIdx.x * blockDim.x + threadIdx.x;
    long long total = (long long)M * 16;      // C=64 -> 16 float4 per node
    if (i >= total) return;
    int node = (int)(i / 16);
    int c = (int)(i % 16) * 4;
    int gph = load_idx(batch, node, is64);
    float4 v = *(const float4*)&H[(long long)node * 64 + c];
    float4 s = *(const float4*)&coef[c];
    float4 t = *(const float4*)&coef[256 + c];
    v.x = fmaf(v.x, s.x, t.x); v.y = fmaf(v.y, s.y, t.y);
    v.z = fmaf(v.z, s.z, t.z); v.w = fmaf(v.w, s.w, t.w);
    float* p = &P[(long long)gph * 64 + c];
    asm volatile("red.global.add.v4.f32 [%0], {%1, %2, %3, %4};"
                 :: "l"(p), "f"(v.x), "f"(v.y), "f"(v.z), "f"(v.w) : "memory");
}

__global__ void head_kernel(const float* __restrict__ P,
                            const float* __restrict__ Wf1, const float* __restrict__ bf1,
                            const float* __restrict__ Wf2, const float* __restrict__ bf2,
                            float* __restrict__ out, int G) {
    int g = blockIdx.x * blockDim.x + threadIdx.x;
    if (g >= G) return;
    float acc[16];
#pragma unroll
    for (int j = 0; j < 16; j++) acc[j] = bf1[j];
    const float* p = &P[(long long)g * 64];
    for (int k = 0; k < 64; k++) {
        float pv = p[k];
#pragma unroll
        for (int j = 0; j < 16; j++) acc[j] = fmaf(pv, Wf1[k * 16 + j], acc[j]);
    }
    float o = bf2[0];
#pragma unroll
    for (int j = 0; j < 16; j++) o = fmaf(fmaxf(acc[j], 0.f), Wf2[j], o);
    out[g] = fmaxf(o, 0.f);
}

// ---------------- host launcher ----------------
static void launch_transpose(const float* W, uint32_t* BtHi, uint32_t* BtLo,
                             int K, int N, const float* scale) {
    dim3 grid((N + 31) / 32, (K + 31) / 32);
    transpose_w_split<<<grid, dim3(32, 8)>>>(W, BtHi, BtLo, K, N, scale);
}

static void launch_scatter(const float* Y, float* A, const void* eidx, int E, int C4) {
    long long total = (long long)E * C4;
    long long half = (total + 1) >> 1;
    scatter_add<<<(int)((half + 255) / 256), 256>>>(Y, A, eidx, E, C4);
}

template <int BN_, int WM_, int WN_, int RELUIN, int VEC4, int STATS>
static void launch_gemm(const float* A, const uint32_t* BtHi, const uint32_t* BtLo,
                        float* C, int M, int N, int K, const float* bias,
                        int reluOut, float* C2, const float* bias2, float* stats) {
    constexpr int SMEM_BYTES = (2 * 128 * 36 + 4 * BN_ * 20) * 4;
    static bool attr_set = false;
    if (!attr_set) {
        cudaFuncSetAttribute(mma_gemm<BN_, WM_, WN_, RELUIN, VEC4, STATS>,
                             cudaFuncAttributeMaxDynamicSharedMemorySize, SMEM_BYTES);
        attr_set = true;
    }
    dim3 grid(N / BN_, (M + 127) / 128);
    mma_gemm<BN_, WM_, WN_, RELUIN, VEC4, STATS><<<grid, 256, SMEM_BYTES>>>(
        A, BtHi, BtLo, C, M, N, K, bias, reluOut, C2, bias2, stats);
}

extern "C" void kernel_launch(void* const* d_in, const int* in_sizes, int n_in,
                              void* d_out, int out_size) {
    const float* x    = (const float*)d_in[0];
    const void*  eidx = d_in[1];
    const void*  batc = d_in[2];
    const float* W1a = (const float*)d_in[3];  const float* b1a = (const float*)d_in[4];
    const float* W1b = (const float*)d_in[5];  const float* b1b = (const float*)d_in[6];
    const float* g1  = (const float*)d_in[7];  const float* be1 = (const float*)d_in[8];
    const float* W2a = (const float*)d_in[9];  const float* b2a = (const float*)d_in[10];
    const float* W2b = (const float*)d_in[11]; const float* b2b = (const float*)d_in[12];
    const float* g2  = (const float*)d_in[13]; const float* be2 = (const float*)d_in[14];
    const float* W3a = (const float*)d_in[15]; const float* b3a = (const float*)d_in[16];
    const float* W3b = (const float*)d_in[17]; const float* b3b = (const float*)d_in[18];
    const float* g3  = (const float*)d_in[19]; const float* be3 = (const float*)d_in[20];
    const float* Wf1 = (const float*)d_in[21]; const float* bf1 = (const float*)d_in[22];
    const float* Wf2 = (const float*)d_in[23]; const float* bf2 = (const float*)d_in[24];

    float *Y, *A, *H1, *H2, *H3, *P, *ST, *CF, *BY, *BA;
    uint32_t *BH, *BL;
    cudaGetSymbolAddress((void**)&Y,  g_Y);
    cudaGetSymbolAddress((void**)&A,  g_A);
    cudaGetSymbolAddress((void**)&H1, g_H1);
    cudaGetSymbolAddress((void**)&H2, g_H2);
    cudaGetSymbolAddress((void**)&H3, g_H3);
    cudaGetSymbolAddress((void**)&P,  g_pool);
    cudaGetSymbolAddress((void**)&ST, g_stats);
    cudaGetSymbolAddress((void**)&CF, g_coef);
    cudaGetSymbolAddress((void**)&BY, g_biasY);
    cudaGetSymbolAddress((void**)&BA, g_biasA);
    cudaGetSymbolAddress((void**)&BH, g_BtHi);
    cudaGetSymbolAddress((void**)&BL, g_BtLo);

    detect_dtype<<<1, 256>>>((const unsigned int*)eidx, 1024);

    const int M = NN;

    // ---- Layer 1: 373 -> 256 (no BN on input; K=373 -> scalar A staging) ----
    launch_transpose(W1a, BH, BL, 373, 256, nullptr);
    launch_gemm<128, 2, 4, 0, 0, 0>(x, BH, BL, Y, M, 256, 373, nullptr, 0, A, b1a, nullptr);
    launch_scatter(Y, A, eidx, NE, 64);
    launch_transpose(W1b, BH, BL, 256, 256, nullptr);
    launch_gemm<128, 2, 4, 1, 1, 1>(A, BH, BL, H1, M, 256, 256, b1b, 1, nullptr, nullptr, ST);
    bn_coef<<<1, 512>>>(256, g1, be1, ST, CF);

    // ---- Layer 2: 256 -> 128 (BN1 folded into W2a) ----
    launch_transpose(W2a, BH, BL, 256, 128, CF);
    vecmat_bias<<<1, 128>>>(W2a, CF, b2a, BY, BA, 256, 128);
    launch_gemm<128, 2, 4, 0, 1, 0>(H1, BH, BL, Y, M, 128, 256, BY, 0, A, BA, nullptr);
    launch_scatter(Y, A, eidx, NE, 32);
    launch_transpose(W2b, BH, BL, 128, 128, nullptr);
    launch_gemm<128, 2, 4, 1, 1, 1>(A, BH, BL, H2, M, 128, 128, b2b, 1, nullptr, nullptr, ST);
    bn_coef<<<1, 512>>>(128, g2, be2, ST, CF);

    // ---- Layer 3: 128 -> 64 (BN2 folded into W3a) ----
    launch_transpose(W3a, BH, BL, 128, 64, CF);
    vecmat_bias<<<1, 64>>>(W3a, CF, b3a, BY, BA, 128, 64);
    launch_gemm<64, 4, 2, 0, 1, 0>(H2, BH, BL, Y, M, 64, 128, BY, 0, A, BA, nullptr);
    launch_scatter(Y, A, eidx, NE, 16);
    launch_transpose(W3b, BH, BL, 64, 64, nullptr);
    launch_gemm<64, 4, 2, 1, 1, 1>(A, BH, BL, H3, M, 64, 64, b3b, 1, nullptr, nullptr, ST);
    bn_coef<<<1, 512>>>(64, g3, be3, ST, CF);

    // ---- Pool (BN3 inline) + head ----
    zero_f<<<(NG * 64 + 255) / 256, 256>>>(P, NG * 64);
    {
        long long tot = (long long)M * 16;
        pool_bn_add<<<(int)((tot + 255) / 256), 256>>>(H3, P, batc, CF, M);
    }
    head_kernel<<<(NG + 127) / 128, 128>>>(P, Wf1, bf1, Wf2, bf2, (float*)d_out, NG);
}